// round 3
// baseline (speedup 1.0000x reference)
#include <cuda_runtime.h>
#include <cstdint>

// ---------------------------------------------------------------------------
// SVACrossAttentionLayer: LN -> Q/K/V proj -> 16-head cross attn (typed bias +
// padding mask) -> out proj -> residual LN.   B=2, Nq=1024, Nk=4096, HID=1024,
// H=16, hd=64.  All fp32 (R2: mask dtype fix — read as 32-bit words).
// ---------------------------------------------------------------------------

#define B_       2
#define NQ       1024
#define NK       4096
#define HID      1024
#define HEADS    16
#define HD       64
#define LN_EPS   1e-5f
#define NEG_BIG  (-1e30f)
#define M_INIT   (-1e9f)

// ------------------------- scratch (static, no allocs) ---------------------
__device__ float g_qn  [B_ * NQ * HID];   // 8 MB
__device__ float g_kvn [B_ * NK * HID];   // 32 MB
__device__ float g_q   [B_ * NQ * HID];   // 8 MB
__device__ float g_k   [B_ * NK * HID];   // 32 MB
__device__ float g_v   [B_ * NK * HID];   // 32 MB
__device__ float g_att [B_ * NQ * HID];   // 8 MB
__device__ float g_proj[B_ * NQ * HID];   // 8 MB

// ------------------------- block reduce (256 thr) ---------------------------
__device__ __forceinline__ void block_reduce2(float& s, float& ss) {
    #pragma unroll
    for (int o = 16; o; o >>= 1) {
        s  += __shfl_xor_sync(0xffffffffu, s,  o);
        ss += __shfl_xor_sync(0xffffffffu, ss, o);
    }
    __shared__ float sh[2][8];
    int w = threadIdx.x >> 5, lane = threadIdx.x & 31;
    if (lane == 0) { sh[0][w] = s; sh[1][w] = ss; }
    __syncthreads();
    float ts = 0.f, tss = 0.f;
    #pragma unroll
    for (int k = 0; k < 8; ++k) { ts += sh[0][k]; tss += sh[1][k]; }
    s = ts; ss = tss;
    __syncthreads();
}

// ------------------------- LayerNorm (one block / row) ----------------------
__global__ void __launch_bounds__(256) ln_kernel(
    const float* __restrict__ x, float* __restrict__ y,
    const float* __restrict__ w, const float* __restrict__ b) {
    int row = blockIdx.x;
    const float4* x4 = (const float4*)(x + (size_t)row * HID);
    int t = threadIdx.x;                     // 256 threads * float4 = 1024
    float4 v = x4[t];
    float s  = v.x + v.y + v.z + v.w;
    float ss = v.x*v.x + v.y*v.y + v.z*v.z + v.w*v.w;
    block_reduce2(s, ss);
    float mean = s * (1.0f / HID);
    float var  = ss * (1.0f / HID) - mean * mean;
    float rstd = rsqrtf(var + LN_EPS);
    const float4* w4 = (const float4*)w;
    const float4* b4 = (const float4*)b;
    float4 wv = w4[t], bv = b4[t], o;
    o.x = (v.x - mean) * rstd * wv.x + bv.x;
    o.y = (v.y - mean) * rstd * wv.y + bv.y;
    o.z = (v.z - mean) * rstd * wv.z + bv.z;
    o.w = (v.w - mean) * rstd * wv.w + bv.w;
    ((float4*)(y + (size_t)row * HID))[t] = o;
}

// ------------------------- residual + LayerNorm ------------------------------
__global__ void __launch_bounds__(256) addln_kernel(
    const float* __restrict__ xq, const float* __restrict__ xp,
    float* __restrict__ y,
    const float* __restrict__ w, const float* __restrict__ b) {
    int row = blockIdx.x;
    const float4* q4 = (const float4*)(xq + (size_t)row * HID);
    const float4* p4 = (const float4*)(xp + (size_t)row * HID);
    int t = threadIdx.x;
    float4 a = q4[t], c = p4[t], v;
    v.x = a.x + c.x; v.y = a.y + c.y; v.z = a.z + c.z; v.w = a.w + c.w;
    float s  = v.x + v.y + v.z + v.w;
    float ss = v.x*v.x + v.y*v.y + v.z*v.z + v.w*v.w;
    block_reduce2(s, ss);
    float mean = s * (1.0f / HID);
    float var  = ss * (1.0f / HID) - mean * mean;
    float rstd = rsqrtf(var + LN_EPS);
    const float4* w4 = (const float4*)w;
    const float4* b4 = (const float4*)b;
    float4 wv = w4[t], bv = b4[t], o;
    o.x = (v.x - mean) * rstd * wv.x + bv.x;
    o.y = (v.y - mean) * rstd * wv.y + bv.y;
    o.z = (v.z - mean) * rstd * wv.z + bv.z;
    o.w = (v.w - mean) * rstd * wv.w + bv.w;
    ((float4*)(y + (size_t)row * HID))[t] = o;
}

// ------------------------- GEMM  C[M,1024] = A[M,1024] @ W[1024,1024]^T ------
// Both operands are K-major (dot over contiguous rows). 64x64 tile, BK=64,
// 128 threads, 8x4 microtile per thread, smem stored k-major (transposed).
__global__ void __launch_bounds__(128) gemm_nt(
    const float* __restrict__ A, const float* __restrict__ W,
    float* __restrict__ C) {
    __shared__ float As[64][65];
    __shared__ float Ws[64][65];
    int tid = threadIdx.x;
    int tx = tid & 15, ty = tid >> 4;         // tx: 16 col groups, ty: 8 row groups
    int m0 = blockIdx.y * 64, n0 = blockIdx.x * 64;
    float acc[8][4] = {};
    for (int kt = 0; kt < HID; kt += 64) {
        #pragma unroll
        for (int l = 0; l < 8; ++l) {
            int i   = tid + l * 128;          // 0..1023
            int row = i >> 4;
            int kq  = i & 15;
            float4 a = *(const float4*)(A + (size_t)(m0 + row) * HID + kt + kq * 4);
            As[kq*4+0][row] = a.x; As[kq*4+1][row] = a.y;
            As[kq*4+2][row] = a.z; As[kq*4+3][row] = a.w;
            float4 wv = *(const float4*)(W + (size_t)(n0 + row) * HID + kt + kq * 4);
            Ws[kq*4+0][row] = wv.x; Ws[kq*4+1][row] = wv.y;
            Ws[kq*4+2][row] = wv.z; Ws[kq*4+3][row] = wv.w;
        }
        __syncthreads();
        #pragma unroll 8
        for (int kk = 0; kk < 64; ++kk) {
            float af[8], wf[4];
            #pragma unroll
            for (int r = 0; r < 8; ++r) af[r] = As[kk][ty*8 + r];
            #pragma unroll
            for (int c = 0; c < 4; ++c) wf[c] = Ws[kk][tx*4 + c];
            #pragma unroll
            for (int r = 0; r < 8; ++r)
                #pragma unroll
                for (int c = 0; c < 4; ++c)
                    acc[r][c] += af[r] * wf[c];
        }
        __syncthreads();
    }
    #pragma unroll
    for (int r = 0; r < 8; ++r) {
        float4 o = make_float4(acc[r][0], acc[r][1], acc[r][2], acc[r][3]);
        *(float4*)(C + (size_t)(m0 + ty*8 + r) * HID + n0 + tx*4) = o;
    }
}

// ------------------------- flash attention ----------------------------------
// One block per (q-tile of 64, head, batch). 128 threads. Online softmax with
// masked = -1e30 and running-max init -1e9 (no -inf arithmetic, no NaNs).
struct AttnSmem {
    float Qs[64][65];      // [d][i]  (k-major)
    float Ks[64][65];      // [d][j]
    float Vs[64][64];      // [j][d]
    float Pt[64][65];      // [j][i]  scores then probabilities
    float rowm[64], rowl[64], alpha[64], colbias[64];
    int   qt[64], ktyp[64];
    float tb[9];
};

__global__ void __launch_bounds__(128) attn_kernel(
    const float* __restrict__ Q, const float* __restrict__ K,
    const float* __restrict__ V,
    const int* __restrict__ qtid, const int* __restrict__ ktid,
    const int* __restrict__ mask,          // bool widened to 32-bit words;
                                           // nonzero bit-pattern == True
    const float* __restrict__ tbias,
    float* __restrict__ O) {
    extern __shared__ char smem_raw[];
    AttnSmem& s = *(AttnSmem*)smem_raw;
    int tid = threadIdx.x;
    int tx = tid & 15, ty = tid >> 4;
    int b = blockIdx.z, h = blockIdx.y, q0 = blockIdx.x * 64;

    if (tid < 64) {
        s.rowm[tid] = M_INIT;
        s.rowl[tid] = 0.f;
        s.qt[tid]   = qtid[q0 + tid];
    }
    if (tid < 9) s.tb[tid] = tbias[tid];

    // Q tile -> smem transposed
    #pragma unroll
    for (int l = 0; l < 8; ++l) {
        int i = tid + l * 128; int row = i >> 4; int kq = i & 15;
        float4 a = *(const float4*)(Q + (size_t)(b*NQ + q0 + row) * HID + h*HD + kq*4);
        s.Qs[kq*4+0][row] = a.x; s.Qs[kq*4+1][row] = a.y;
        s.Qs[kq*4+2][row] = a.z; s.Qs[kq*4+3][row] = a.w;
    }

    int qtr[8];
    float o[8][4] = {};
    // wait for qt[] before reading it
    __syncthreads();
    #pragma unroll
    for (int r = 0; r < 8; ++r) qtr[r] = s.qt[ty*8 + r];

    for (int k0 = 0; k0 < NK; k0 += 64) {
        // load K (transposed) and V (direct) tiles
        #pragma unroll
        for (int l = 0; l < 8; ++l) {
            int i = tid + l * 128; int row = i >> 4; int kq = i & 15;
            size_t base = (size_t)(b*NK + k0 + row) * HID + h*HD + kq*4;
            float4 a = *(const float4*)(K + base);
            s.Ks[kq*4+0][row] = a.x; s.Ks[kq*4+1][row] = a.y;
            s.Ks[kq*4+2][row] = a.z; s.Ks[kq*4+3][row] = a.w;
            float4 vv = *(const float4*)(V + base);
            *(float4*)&s.Vs[row][kq*4] = vv;
        }
        if (tid < 64) {
            s.ktyp[tid]    = ktid[k0 + tid];
            // mask is a widened bool: int32 (0x1) or float32 (0x3F800000) —
            // either way True has a nonzero 32-bit pattern, False is 0.
            s.colbias[tid] = (mask[b*NK + k0 + tid] != 0) ? 0.f : NEG_BIG;
        }
        __syncthreads();

        // S = Q @ K^T  (8x4 microtile)
        float sacc[8][4] = {};
        #pragma unroll 8
        for (int d = 0; d < 64; ++d) {
            float qf[8], kf[4];
            #pragma unroll
            for (int r = 0; r < 8; ++r) qf[r] = s.Qs[d][ty*8 + r];
            #pragma unroll
            for (int c = 0; c < 4; ++c) kf[c] = s.Ks[d][tx*4 + c];
            #pragma unroll
            for (int r = 0; r < 8; ++r)
                #pragma unroll
                for (int c = 0; c < 4; ++c)
                    sacc[r][c] += qf[r] * kf[c];
        }
        // epilogue: scale + typed bias + mask; store transposed
        #pragma unroll
        for (int c = 0; c < 4; ++c) {
            int j = tx*4 + c;
            float cb = s.colbias[j];
            int kty  = s.ktyp[j];
            #pragma unroll
            for (int r = 0; r < 8; ++r) {
                int i = ty*8 + r;
                s.Pt[j][i] = sacc[r][c] * 0.125f + s.tb[qtr[r]*3 + kty] + cb;
            }
        }
        __syncthreads();

        // online softmax update (one thread per q-row)
        if (tid < 64) {
            int i = tid;
            float m_old = s.rowm[i];
            float mx = m_old;
            #pragma unroll 8
            for (int j = 0; j < 64; ++j) mx = fmaxf(mx, s.Pt[j][i]);
            float sum = 0.f;
            #pragma unroll 8
            for (int j = 0; j < 64; ++j) {
                float p = __expf(s.Pt[j][i] - mx);
                s.Pt[j][i] = p;
                sum += p;
            }
            float a = __expf(m_old - mx);
            s.alpha[i] = a;
            s.rowm[i]  = mx;
            s.rowl[i]  = s.rowl[i] * a + sum;
        }
        __syncthreads();

        // O = O*alpha + P @ V
        float ar[8];
        #pragma unroll
        for (int r = 0; r < 8; ++r) ar[r] = s.alpha[ty*8 + r];
        #pragma unroll
        for (int r = 0; r < 8; ++r)
            #pragma unroll
            for (int c = 0; c < 4; ++c)
                o[r][c] *= ar[r];
        #pragma unroll 8
        for (int j = 0; j < 64; ++j) {
            float  pf[8];
            float4 vf = *(const float4*)&s.Vs[j][tx*4];
            #pragma unroll
            for (int r = 0; r < 8; ++r) pf[r] = s.Pt[j][ty*8 + r];
            #pragma unroll
            for (int r = 0; r < 8; ++r) {
                o[r][0] += pf[r] * vf.x;
                o[r][1] += pf[r] * vf.y;
                o[r][2] += pf[r] * vf.z;
                o[r][3] += pf[r] * vf.w;
            }
        }
        __syncthreads();
    }

    #pragma unroll
    for (int r = 0; r < 8; ++r) {
        float inv = 1.0f / s.rowl[ty*8 + r];
        float4 res = make_float4(o[r][0]*inv, o[r][1]*inv, o[r][2]*inv, o[r][3]*inv);
        *(float4*)(O + (size_t)(b*NQ + q0 + ty*8 + r) * HID + h*HD + tx*4) = res;
    }
}

// ---------------------------------------------------------------------------
extern "C" void kernel_launch(void* const* d_in, const int* in_sizes, int n_in,
                              void* d_out, int out_size) {
    const float*         queries = (const float*)d_in[0];
    const float*         kv      = (const float*)d_in[1];
    const int*           qtid    = (const int*)d_in[2];
    const int*           ktid    = (const int*)d_in[3];
    const int*           mask    = (const int*)d_in[4];   // widened bool
    const float*         Wq      = (const float*)d_in[5];
    const float*         Wk      = (const float*)d_in[6];
    const float*         Wv      = (const float*)d_in[7];
    const float*         Wo      = (const float*)d_in[8];
    const float*         qn_w    = (const float*)d_in[9];
    const float*         qn_b    = (const float*)d_in[10];
    const float*         kvn_w   = (const float*)d_in[11];
    const float*         kvn_b   = (const float*)d_in[12];
    const float*         on_w    = (const float*)d_in[13];
    const float*         on_b    = (const float*)d_in[14];
    const float*         tbias   = (const float*)d_in[15];
    float*               out     = (float*)d_out;

    float *qn, *kvn, *q, *k, *v, *att, *proj;
    cudaGetSymbolAddress((void**)&qn,   g_qn);
    cudaGetSymbolAddress((void**)&kvn,  g_kvn);
    cudaGetSymbolAddress((void**)&q,    g_q);
    cudaGetSymbolAddress((void**)&k,    g_k);
    cudaGetSymbolAddress((void**)&v,    g_v);
    cudaGetSymbolAddress((void**)&att,  g_att);
    cudaGetSymbolAddress((void**)&proj, g_proj);

    // allow 66KB+ dynamic smem for the attention kernel (idempotent)
    cudaFuncSetAttribute(attn_kernel, cudaFuncAttributeMaxDynamicSharedMemorySize,
                         (int)sizeof(AttnSmem));

    // 1) LayerNorms
    ln_kernel<<<B_ * NQ, 256>>>(queries, qn, qn_w, qn_b);
    ln_kernel<<<B_ * NK, 256>>>(kv, kvn, kvn_w, kvn_b);

    // 2) projections
    gemm_nt<<<dim3(HID/64, (B_*NQ)/64), 128>>>(qn,  Wq, q);
    gemm_nt<<<dim3(HID/64, (B_*NK)/64), 128>>>(kvn, Wk, k);
    gemm_nt<<<dim3(HID/64, (B_*NK)/64), 128>>>(kvn, Wv, v);

    // 3) attention
    attn_kernel<<<dim3(NQ/64, HEADS, B_), 128, sizeof(AttnSmem)>>>(
        q, k, v, qtid, ktid, mask, tbias, att);

    // 4) out projection
    gemm_nt<<<dim3(HID/64, (B_*NQ)/64), 128>>>(att, Wo, proj);

    // 5) residual + LN
    addln_kernel<<<B_ * NQ, 256>>>(queries, proj, out, on_w, on_b);
}

// round 4
// speedup vs baseline: 1.0577x; 1.0577x over previous
#include <cuda_runtime.h>
#include <cstdint>

// ---------------------------------------------------------------------------
// SVACrossAttentionLayer: LN -> Q/K/V proj -> 16-head cross attn (typed bias +
// padding mask) -> out proj -> residual LN.  B=2, Nq=1024, Nk=4096, HID=1024,
// H=16, hd=64.  R4: 8x8-microtile GEMM + 128x128 attention tiles.
// ---------------------------------------------------------------------------

#define B_       2
#define NQ       1024
#define NK       4096
#define HID      1024
#define HEADS    16
#define HD       64
#define LN_EPS   1e-5f
#define NEG_BIG  (-1e30f)
#define M_INIT   (-1e9f)

// ------------------------- scratch (static, no allocs) ---------------------
__device__ float g_qn  [B_ * NQ * HID];
__device__ float g_kvn [B_ * NK * HID];
__device__ float g_q   [B_ * NQ * HID];
__device__ float g_k   [B_ * NK * HID];
__device__ float g_v   [B_ * NK * HID];
__device__ float g_att [B_ * NQ * HID];
__device__ float g_proj[B_ * NQ * HID];

// ------------------------- block reduce (256 thr) ---------------------------
__device__ __forceinline__ void block_reduce2(float& s, float& ss) {
    #pragma unroll
    for (int o = 16; o; o >>= 1) {
        s  += __shfl_xor_sync(0xffffffffu, s,  o);
        ss += __shfl_xor_sync(0xffffffffu, ss, o);
    }
    __shared__ float sh[2][8];
    int w = threadIdx.x >> 5, lane = threadIdx.x & 31;
    if (lane == 0) { sh[0][w] = s; sh[1][w] = ss; }
    __syncthreads();
    float ts = 0.f, tss = 0.f;
    #pragma unroll
    for (int k = 0; k < 8; ++k) { ts += sh[0][k]; tss += sh[1][k]; }
    s = ts; ss = tss;
    __syncthreads();
}

// ------------------------- LayerNorm (one block / row) ----------------------
__global__ void __launch_bounds__(256) ln_kernel(
    const float* __restrict__ x, float* __restrict__ y,
    const float* __restrict__ w, const float* __restrict__ b) {
    int row = blockIdx.x;
    const float4* x4 = (const float4*)(x + (size_t)row * HID);
    int t = threadIdx.x;
    float4 v = x4[t];
    float s  = v.x + v.y + v.z + v.w;
    float ss = v.x*v.x + v.y*v.y + v.z*v.z + v.w*v.w;
    block_reduce2(s, ss);
    float mean = s * (1.0f / HID);
    float var  = ss * (1.0f / HID) - mean * mean;
    float rstd = rsqrtf(var + LN_EPS);
    float4 wv = ((const float4*)w)[t], bv = ((const float4*)b)[t], o;
    o.x = (v.x - mean) * rstd * wv.x + bv.x;
    o.y = (v.y - mean) * rstd * wv.y + bv.y;
    o.z = (v.z - mean) * rstd * wv.z + bv.z;
    o.w = (v.w - mean) * rstd * wv.w + bv.w;
    ((float4*)(y + (size_t)row * HID))[t] = o;
}

// ------------------------- residual + LayerNorm ------------------------------
__global__ void __launch_bounds__(256) addln_kernel(
    const float* __restrict__ xq, const float* __restrict__ xp,
    float* __restrict__ y,
    const float* __restrict__ w, const float* __restrict__ b) {
    int row = blockIdx.x;
    int t = threadIdx.x;
    float4 a = ((const float4*)(xq + (size_t)row * HID))[t];
    float4 c = ((const float4*)(xp + (size_t)row * HID))[t];
    float4 v;
    v.x = a.x + c.x; v.y = a.y + c.y; v.z = a.z + c.z; v.w = a.w + c.w;
    float s  = v.x + v.y + v.z + v.w;
    float ss = v.x*v.x + v.y*v.y + v.z*v.z + v.w*v.w;
    block_reduce2(s, ss);
    float mean = s * (1.0f / HID);
    float var  = ss * (1.0f / HID) - mean * mean;
    float rstd = rsqrtf(var + LN_EPS);
    float4 wv = ((const float4*)w)[t], bv = ((const float4*)b)[t], o;
    o.x = (v.x - mean) * rstd * wv.x + bv.x;
    o.y = (v.y - mean) * rstd * wv.y + bv.y;
    o.z = (v.z - mean) * rstd * wv.z + bv.z;
    o.w = (v.w - mean) * rstd * wv.w + bv.w;
    ((float4*)(y + (size_t)row * HID))[t] = o;
}

// ------------------------- GEMM  C[M,1024] = A[M,1024] @ W[1024,1024]^T ------
// 128x128 tile, BK=16, 256 threads, 8x8 microtile, register-prefetch pipeline.
__global__ void __launch_bounds__(256, 2) gemm_nt(
    const float* __restrict__ A, const float* __restrict__ W,
    float* __restrict__ C) {
    __shared__ float As[16][132];
    __shared__ float Ws[16][132];
    int tid = threadIdx.x;
    int tx = tid & 15, ty = tid >> 4;
    int m0 = blockIdx.y * 128, n0 = blockIdx.x * 128;

    float4 pa[2], pw[2];
    #pragma unroll
    for (int s = 0; s < 2; ++s) {
        int idx = tid + s * 256;
        int row = idx >> 2, kq = idx & 3;
        pa[s] = *(const float4*)(A + (size_t)(m0 + row) * HID + kq * 4);
        pw[s] = *(const float4*)(W + (size_t)(n0 + row) * HID + kq * 4);
    }

    float acc[8][8] = {};
    for (int kt = 0; kt < 64; ++kt) {
        #pragma unroll
        for (int s = 0; s < 2; ++s) {
            int idx = tid + s * 256;
            int row = idx >> 2, kq = idx & 3;
            As[kq*4+0][row] = pa[s].x; As[kq*4+1][row] = pa[s].y;
            As[kq*4+2][row] = pa[s].z; As[kq*4+3][row] = pa[s].w;
            Ws[kq*4+0][row] = pw[s].x; Ws[kq*4+1][row] = pw[s].y;
            Ws[kq*4+2][row] = pw[s].z; Ws[kq*4+3][row] = pw[s].w;
        }
        __syncthreads();
        if (kt < 63) {
            int kof = (kt + 1) * 16;
            #pragma unroll
            for (int s = 0; s < 2; ++s) {
                int idx = tid + s * 256;
                int row = idx >> 2, kq = idx & 3;
                pa[s] = *(const float4*)(A + (size_t)(m0 + row) * HID + kof + kq * 4);
                pw[s] = *(const float4*)(W + (size_t)(n0 + row) * HID + kof + kq * 4);
            }
        }
        #pragma unroll
        for (int kk = 0; kk < 16; ++kk) {
            float4 a0 = *(const float4*)&As[kk][ty*8];
            float4 a1 = *(const float4*)&As[kk][ty*8+4];
            float4 w0 = *(const float4*)&Ws[kk][tx*8];
            float4 w1 = *(const float4*)&Ws[kk][tx*8+4];
            float af[8] = {a0.x,a0.y,a0.z,a0.w,a1.x,a1.y,a1.z,a1.w};
            float wf[8] = {w0.x,w0.y,w0.z,w0.w,w1.x,w1.y,w1.z,w1.w};
            #pragma unroll
            for (int r = 0; r < 8; ++r)
                #pragma unroll
                for (int c = 0; c < 8; ++c)
                    acc[r][c] += af[r] * wf[c];
        }
        __syncthreads();
    }
    #pragma unroll
    for (int r = 0; r < 8; ++r) {
        float* crow = C + (size_t)(m0 + ty*8 + r) * HID + n0 + tx*8;
        *(float4*)(crow    ) = make_float4(acc[r][0], acc[r][1], acc[r][2], acc[r][3]);
        *(float4*)(crow + 4) = make_float4(acc[r][4], acc[r][5], acc[r][6], acc[r][7]);
    }
}

// ------------------------- flash attention ----------------------------------
// Block: 128 q-rows x one head x one batch; K-tiles of 128. 256 threads.
// S-MMA: 8x8 microtile (16x16 thread grid over 128x128 S tile).
// PV-MMA: 8x4 microtile (128 q x 64 d O tile).
// Softmax parallel over all 256 threads (2 threads/row).
struct AttnSmem {
    float Qs[64][132];     // [d][i]   (k-major)
    float Ks[64][132];     // [d][j]
    float Vs[128][68];     // [j][d]
    float Pt[128][132];    // [j][i]   scores then probabilities
    float rowm[128], rowl[128], alpha[128], colbias[128];
    int   qt[128], ktyp[128];
    float tb[9];
};

__global__ void __launch_bounds__(256) attn_kernel(
    const float* __restrict__ Q, const float* __restrict__ K,
    const float* __restrict__ V,
    const int* __restrict__ qtid, const int* __restrict__ ktid,
    const int* __restrict__ mask,   // widened bool: nonzero word == True
    const float* __restrict__ tbias,
    float* __restrict__ O) {
    extern __shared__ char smem_raw[];
    AttnSmem& s = *(AttnSmem*)smem_raw;
    int tid = threadIdx.x;
    int tx = tid & 15, ty = tid >> 4;
    int b = blockIdx.z, h = blockIdx.y, q0 = blockIdx.x * 128;

    if (tid < 128) {
        s.rowm[tid] = M_INIT;
        s.rowl[tid] = 0.f;
        s.qt[tid]   = qtid[q0 + tid];
    }
    if (tid < 9) s.tb[tid] = tbias[tid];

    // Q tile (128 x 64) -> smem transposed
    #pragma unroll
    for (int l = 0; l < 8; ++l) {
        int i = tid + l * 256; int row = i >> 4; int kq = i & 15;
        float4 a = *(const float4*)(Q + (size_t)(b*NQ + q0 + row) * HID + h*HD + kq*4);
        s.Qs[kq*4+0][row] = a.x; s.Qs[kq*4+1][row] = a.y;
        s.Qs[kq*4+2][row] = a.z; s.Qs[kq*4+3][row] = a.w;
    }

    float o[8][4] = {};
    __syncthreads();
    int qtr[8];
    #pragma unroll
    for (int r = 0; r < 8; ++r) qtr[r] = s.qt[ty*8 + r];

    for (int k0 = 0; k0 < NK; k0 += 128) {
        // load K (transposed) and V (direct) tiles: 128 rows x 64 d
        #pragma unroll
        for (int l = 0; l < 8; ++l) {
            int i = tid + l * 256; int row = i >> 4; int kq = i & 15;
            size_t base = (size_t)(b*NK + k0 + row) * HID + h*HD + kq*4;
            float4 a = *(const float4*)(K + base);
            s.Ks[kq*4+0][row] = a.x; s.Ks[kq*4+1][row] = a.y;
            s.Ks[kq*4+2][row] = a.z; s.Ks[kq*4+3][row] = a.w;
            float4 vv = *(const float4*)(V + base);
            *(float4*)&s.Vs[row][kq*4] = vv;
        }
        if (tid < 128) {
            s.ktyp[tid]    = ktid[k0 + tid];
            s.colbias[tid] = (mask[b*NK + k0 + tid] != 0) ? 0.f : NEG_BIG;
        }
        __syncthreads();

        // S = Q @ K^T  (8x8 microtile over 128x128)
        float sacc[8][8] = {};
        #pragma unroll 8
        for (int d = 0; d < 64; ++d) {
            float4 q0v = *(const float4*)&s.Qs[d][ty*8];
            float4 q1v = *(const float4*)&s.Qs[d][ty*8+4];
            float4 k0v = *(const float4*)&s.Ks[d][tx*8];
            float4 k1v = *(const float4*)&s.Ks[d][tx*8+4];
            float qf[8] = {q0v.x,q0v.y,q0v.z,q0v.w,q1v.x,q1v.y,q1v.z,q1v.w};
            float kf[8] = {k0v.x,k0v.y,k0v.z,k0v.w,k1v.x,k1v.y,k1v.z,k1v.w};
            #pragma unroll
            for (int r = 0; r < 8; ++r)
                #pragma unroll
                for (int c = 0; c < 8; ++c)
                    sacc[r][c] += qf[r] * kf[c];
        }
        // epilogue: scale + typed bias + mask; store transposed (vectorized)
        #pragma unroll
        for (int c = 0; c < 8; ++c) {
            int j = tx*8 + c;
            float cb = s.colbias[j];
            int kty  = s.ktyp[j];
            float tmp[8];
            #pragma unroll
            for (int r = 0; r < 8; ++r)
                tmp[r] = sacc[r][c] * 0.125f + s.tb[qtr[r]*3 + kty] + cb;
            *(float4*)&s.Pt[j][ty*8]   = make_float4(tmp[0],tmp[1],tmp[2],tmp[3]);
            *(float4*)&s.Pt[j][ty*8+4] = make_float4(tmp[4],tmp[5],tmp[6],tmp[7]);
        }
        __syncthreads();

        // online softmax: 2 threads per q-row, 64 keys each
        {
            int i = tid >> 1, half = tid & 1;
            float m_old = s.rowm[i];
            float mx = M_INIT;
            #pragma unroll 8
            for (int jj = 0; jj < 64; ++jj)
                mx = fmaxf(mx, s.Pt[half*64 + jj][i]);
            mx = fmaxf(mx, __shfl_xor_sync(0xffffffffu, mx, 1));
            mx = fmaxf(mx, m_old);
            float sum = 0.f;
            #pragma unroll 8
            for (int jj = 0; jj < 64; ++jj) {
                int j = half*64 + jj;
                float p = __expf(s.Pt[j][i] - mx);
                s.Pt[j][i] = p;
                sum += p;
            }
            sum += __shfl_xor_sync(0xffffffffu, sum, 1);
            if (!half) {
                float a = __expf(m_old - mx);
                s.alpha[i] = a;
                s.rowm[i]  = mx;
                s.rowl[i]  = s.rowl[i] * a + sum;
            }
        }
        __syncthreads();

        // O = O*alpha + P @ V   (8 rows x 4 d per thread)
        float ar[8];
        #pragma unroll
        for (int r = 0; r < 8; ++r) ar[r] = s.alpha[ty*8 + r];
        #pragma unroll
        for (int r = 0; r < 8; ++r)
            #pragma unroll
            for (int c = 0; c < 4; ++c)
                o[r][c] *= ar[r];
        #pragma unroll 8
        for (int j = 0; j < 128; ++j) {
            float4 vf = *(const float4*)&s.Vs[j][tx*4];
            float4 p0 = *(const float4*)&s.Pt[j][ty*8];
            float4 p1 = *(const float4*)&s.Pt[j][ty*8+4];
            float pf[8] = {p0.x,p0.y,p0.z,p0.w,p1.x,p1.y,p1.z,p1.w};
            #pragma unroll
            for (int r = 0; r < 8; ++r) {
                o[r][0] += pf[r] * vf.x;
                o[r][1] += pf[r] * vf.y;
                o[r][2] += pf[r] * vf.z;
                o[r][3] += pf[r] * vf.w;
            }
        }
        __syncthreads();
    }

    #pragma unroll
    for (int r = 0; r < 8; ++r) {
        float inv = 1.0f / s.rowl[ty*8 + r];
        float4 res = make_float4(o[r][0]*inv, o[r][1]*inv, o[r][2]*inv, o[r][3]*inv);
        *(float4*)(O + (size_t)(b*NQ + q0 + ty*8 + r) * HID + h*HD + tx*4) = res;
    }
}

// ---------------------------------------------------------------------------
extern "C" void kernel_launch(void* const* d_in, const int* in_sizes, int n_in,
                              void* d_out, int out_size) {
    const float* queries = (const float*)d_in[0];
    const float* kv      = (const float*)d_in[1];
    const int*   qtid    = (const int*)d_in[2];
    const int*   ktid    = (const int*)d_in[3];
    const int*   mask    = (const int*)d_in[4];   // widened bool
    const float* Wq      = (const float*)d_in[5];
    const float* Wk      = (const float*)d_in[6];
    const float* Wv      = (const float*)d_in[7];
    const float* Wo      = (const float*)d_in[8];
    const float* qn_w    = (const float*)d_in[9];
    const float* qn_b    = (const float*)d_in[10];
    const float* kvn_w   = (const float*)d_in[11];
    const float* kvn_b   = (const float*)d_in[12];
    const float* on_w    = (const float*)d_in[13];
    const float* on_b    = (const float*)d_in[14];
    const float* tbias   = (const float*)d_in[15];
    float*       out     = (float*)d_out;

    float *qn, *kvn, *q, *k, *v, *att, *proj;
    cudaGetSymbolAddress((void**)&qn,   g_qn);
    cudaGetSymbolAddress((void**)&kvn,  g_kvn);
    cudaGetSymbolAddress((void**)&q,    g_q);
    cudaGetSymbolAddress((void**)&k,    g_k);
    cudaGetSymbolAddress((void**)&v,    g_v);
    cudaGetSymbolAddress((void**)&att,  g_att);
    cudaGetSymbolAddress((void**)&proj, g_proj);

    cudaFuncSetAttribute(attn_kernel, cudaFuncAttributeMaxDynamicSharedMemorySize,
                         (int)sizeof(AttnSmem));

    // 1) LayerNorms
    ln_kernel<<<B_ * NQ, 256>>>(queries, qn, qn_w, qn_b);
    ln_kernel<<<B_ * NK, 256>>>(kv, kvn, kvn_w, kvn_b);

    // 2) projections
    gemm_nt<<<dim3(HID/128, (B_*NQ)/128), 256>>>(qn,  Wq, q);
    gemm_nt<<<dim3(HID/128, (B_*NK)/128), 256>>>(kvn, Wk, k);
    gemm_nt<<<dim3(HID/128, (B_*NK)/128), 256>>>(kvn, Wv, v);

    // 3) attention
    attn_kernel<<<dim3(NQ/128, HEADS, B_), 256, sizeof(AttnSmem)>>>(
        q, k, v, qtid, ktid, mask, tbias, att);

    // 4) out projection
    gemm_nt<<<dim3(HID/128, (B_*NQ)/128), 256>>>(att, Wo, proj);

    // 5) residual + LN
    addln_kernel<<<B_ * NQ, 256>>>(queries, proj, out, on_w, on_b);
}

// round 7
// speedup vs baseline: 1.4459x; 1.3671x over previous
#include <cuda_runtime.h>
#include <cuda_bf16.h>
#include <cstdint>

// ---------------------------------------------------------------------------
// SVACrossAttentionLayer on GB300.  R6: projection GEMMs on legacy tensor-core
// path (mma.sync m16n8k16 bf16, family-safe for compute_103) with bf16
// split-precision x3 and fp32 accumulation.  Attention remains fp32 SIMT.
// B=2, Nq=1024, Nk=4096, HID=1024, H=16, hd=64.
// ---------------------------------------------------------------------------

#define B_       2
#define NQ       1024
#define NK       4096
#define HID      1024
#define HEADS    16
#define HD       64
#define LN_EPS   1e-5f
#define NEG_BIG  (-1e30f)
#define M_INIT   (-1e9f)

// ------------------------- scratch (static, no allocs) ---------------------
__device__ float         g_q    [B_ * NQ * HID];
__device__ float         g_k    [B_ * NK * HID];
__device__ float         g_v    [B_ * NK * HID];
__device__ float         g_att  [B_ * NQ * HID];
__device__ float         g_proj [B_ * NQ * HID];
__device__ __nv_bfloat16 g_qn_hi [B_ * NQ * HID];
__device__ __nv_bfloat16 g_qn_lo [B_ * NQ * HID];
__device__ __nv_bfloat16 g_kvn_hi[B_ * NK * HID];
__device__ __nv_bfloat16 g_kvn_lo[B_ * NK * HID];
__device__ __nv_bfloat16 g_att_hi[B_ * NQ * HID];
__device__ __nv_bfloat16 g_att_lo[B_ * NQ * HID];
__device__ __nv_bfloat16 g_w_hi  [4 * HID * HID];   // Wq,Wk,Wv,Wo
__device__ __nv_bfloat16 g_w_lo  [4 * HID * HID];

// ------------------------- mma.sync helper ----------------------------------
__device__ __forceinline__ void mma_bf16(
    float& c0, float& c1, float& c2, float& c3,
    uint32_t a0, uint32_t a1, uint32_t a2, uint32_t a3,
    uint32_t b0, uint32_t b1) {
    asm volatile(
        "mma.sync.aligned.m16n8k16.row.col.f32.bf16.bf16.f32 "
        "{%0,%1,%2,%3}, {%4,%5,%6,%7}, {%8,%9}, {%0,%1,%2,%3};"
        : "+f"(c0), "+f"(c1), "+f"(c2), "+f"(c3)
        : "r"(a0), "r"(a1), "r"(a2), "r"(a3), "r"(b0), "r"(b1));
}

// ------------------------- block reduce (256 thr) ---------------------------
__device__ __forceinline__ void block_reduce2(float& s, float& ss) {
    #pragma unroll
    for (int o = 16; o; o >>= 1) {
        s  += __shfl_xor_sync(0xffffffffu, s,  o);
        ss += __shfl_xor_sync(0xffffffffu, ss, o);
    }
    __shared__ float sh[2][8];
    int w = threadIdx.x >> 5, lane = threadIdx.x & 31;
    if (lane == 0) { sh[0][w] = s; sh[1][w] = ss; }
    __syncthreads();
    float ts = 0.f, tss = 0.f;
    #pragma unroll
    for (int k = 0; k < 8; ++k) { ts += sh[0][k]; tss += sh[1][k]; }
    s = ts; ss = tss;
    __syncthreads();
}

// ------------------------- LayerNorm -> split bf16 --------------------------
__global__ void __launch_bounds__(256) ln_cvt_kernel(
    const float* __restrict__ x,
    __nv_bfloat16* __restrict__ hi, __nv_bfloat16* __restrict__ lo,
    const float* __restrict__ w, const float* __restrict__ b) {
    int row = blockIdx.x;
    int t = threadIdx.x;
    float4 v = ((const float4*)(x + (size_t)row * HID))[t];
    float s  = v.x + v.y + v.z + v.w;
    float ss = v.x*v.x + v.y*v.y + v.z*v.z + v.w*v.w;
    block_reduce2(s, ss);
    float mean = s * (1.0f / HID);
    float var  = ss * (1.0f / HID) - mean * mean;
    float rstd = rsqrtf(var + LN_EPS);
    float4 wv = ((const float4*)w)[t], bv = ((const float4*)b)[t];
    float o0 = (v.x - mean) * rstd * wv.x + bv.x;
    float o1 = (v.y - mean) * rstd * wv.y + bv.y;
    float o2 = (v.z - mean) * rstd * wv.z + bv.z;
    float o3 = (v.w - mean) * rstd * wv.w + bv.w;
    __nv_bfloat16 h0 = __float2bfloat16(o0), h1 = __float2bfloat16(o1);
    __nv_bfloat16 h2 = __float2bfloat16(o2), h3 = __float2bfloat16(o3);
    __nv_bfloat16 l0 = __float2bfloat16(o0 - __bfloat162float(h0));
    __nv_bfloat16 l1 = __float2bfloat16(o1 - __bfloat162float(h1));
    __nv_bfloat16 l2 = __float2bfloat16(o2 - __bfloat162float(h2));
    __nv_bfloat16 l3 = __float2bfloat16(o3 - __bfloat162float(h3));
    ((ushort4*)(hi + (size_t)row * HID))[t] =
        make_ushort4(*(unsigned short*)&h0, *(unsigned short*)&h1,
                     *(unsigned short*)&h2, *(unsigned short*)&h3);
    ((ushort4*)(lo + (size_t)row * HID))[t] =
        make_ushort4(*(unsigned short*)&l0, *(unsigned short*)&l1,
                     *(unsigned short*)&l2, *(unsigned short*)&l3);
}

// ------------------------- fp32 -> split bf16 -------------------------------
__global__ void __launch_bounds__(256) cvt_kernel(
    const float* __restrict__ x,
    __nv_bfloat16* __restrict__ hi, __nv_bfloat16* __restrict__ lo, int n4) {
    int i = blockIdx.x * 256 + threadIdx.x;
    if (i >= n4) return;
    float4 v = ((const float4*)x)[i];
    __nv_bfloat16 h0 = __float2bfloat16(v.x), h1 = __float2bfloat16(v.y);
    __nv_bfloat16 h2 = __float2bfloat16(v.z), h3 = __float2bfloat16(v.w);
    __nv_bfloat16 l0 = __float2bfloat16(v.x - __bfloat162float(h0));
    __nv_bfloat16 l1 = __float2bfloat16(v.y - __bfloat162float(h1));
    __nv_bfloat16 l2 = __float2bfloat16(v.z - __bfloat162float(h2));
    __nv_bfloat16 l3 = __float2bfloat16(v.w - __bfloat162float(h3));
    ((ushort4*)hi)[i] = make_ushort4(*(unsigned short*)&h0, *(unsigned short*)&h1,
                                     *(unsigned short*)&h2, *(unsigned short*)&h3);
    ((ushort4*)lo)[i] = make_ushort4(*(unsigned short*)&l0, *(unsigned short*)&l1,
                                     *(unsigned short*)&l2, *(unsigned short*)&l3);
}

// ------------------------- residual + LayerNorm ------------------------------
__global__ void __launch_bounds__(256) addln_kernel(
    const float* __restrict__ xq, const float* __restrict__ xp,
    float* __restrict__ y,
    const float* __restrict__ w, const float* __restrict__ b) {
    int row = blockIdx.x;
    int t = threadIdx.x;
    float4 a = ((const float4*)(xq + (size_t)row * HID))[t];
    float4 c = ((const float4*)(xp + (size_t)row * HID))[t];
    float4 v;
    v.x = a.x + c.x; v.y = a.y + c.y; v.z = a.z + c.z; v.w = a.w + c.w;
    float s  = v.x + v.y + v.z + v.w;
    float ss = v.x*v.x + v.y*v.y + v.z*v.z + v.w*v.w;
    block_reduce2(s, ss);
    float mean = s * (1.0f / HID);
    float var  = ss * (1.0f / HID) - mean * mean;
    float rstd = rsqrtf(var + LN_EPS);
    float4 wv = ((const float4*)w)[t], bv = ((const float4*)b)[t], o;
    o.x = (v.x - mean) * rstd * wv.x + bv.x;
    o.y = (v.y - mean) * rstd * wv.y + bv.y;
    o.z = (v.z - mean) * rstd * wv.z + bv.z;
    o.w = (v.w - mean) * rstd * wv.w + bv.w;
    ((float4*)(y + (size_t)row * HID))[t] = o;
}

// ------------------------- HMMA GEMM ----------------------------------------
// C[M,1024] = A[M,1024] @ W[1024,1024]^T, bf16 split: hi*hi + hi*lo + lo*hi,
// fp32 accumulators.  Block 128x128, BK=64, 8 warps (warp tile 64x32).
// smem tiles padded to 72 bf16/row: fragment LDS banks = 4*group+tig (no
// conflicts).
#define GPAD 72
#define GEMM_SMEM (4 * 128 * GPAD * 2)   // 73728 B

__global__ void __launch_bounds__(256, 2) hmma_gemm(
    const __nv_bfloat16* __restrict__ Ahi, const __nv_bfloat16* __restrict__ Alo,
    const __nv_bfloat16* __restrict__ Whi, const __nv_bfloat16* __restrict__ Wlo,
    float* __restrict__ C) {
    extern __shared__ __nv_bfloat16 smem[];
    __nv_bfloat16* sAhi = smem;
    __nv_bfloat16* sAlo = sAhi + 128 * GPAD;
    __nv_bfloat16* sWhi = sAlo + 128 * GPAD;
    __nv_bfloat16* sWlo = sWhi + 128 * GPAD;
    int tid = threadIdx.x, wid = tid >> 5, lane = tid & 31;
    int group = lane >> 2, tig = lane & 3;
    int m0 = blockIdx.y * 128, n0 = blockIdx.x * 128;
    int wm = (wid >> 2) * 64, wn = (wid & 3) * 32;

    float acc[4][4][4] = {};

    for (int kt = 0; kt < 16; ++kt) {
        #pragma unroll
        for (int l = 0; l < 4; ++l) {
            int idx = tid + l * 256;          // 0..1023
            int row = idx >> 3, c = idx & 7;  // col chunk of 8 bf16
            size_t ga = (size_t)(m0 + row) * HID + kt * 64 + c * 8;
            size_t gw = (size_t)(n0 + row) * HID + kt * 64 + c * 8;
            *(uint4*)&sAhi[row * GPAD + c * 8] = *(const uint4*)&Ahi[ga];
            *(uint4*)&sAlo[row * GPAD + c * 8] = *(const uint4*)&Alo[ga];
            *(uint4*)&sWhi[row * GPAD + c * 8] = *(const uint4*)&Whi[gw];
            *(uint4*)&sWlo[row * GPAD + c * 8] = *(const uint4*)&Wlo[gw];
        }
        __syncthreads();

        #pragma unroll
        for (int ks = 0; ks < 4; ++ks) {
            int kb = ks * 16;
            uint32_t ah[4][4], al[4][4];
            #pragma unroll
            for (int mi = 0; mi < 4; ++mi) {
                int r0 = wm + mi * 16 + group;
                int o00 = r0 * GPAD + kb + tig * 2;
                int o10 = (r0 + 8) * GPAD + kb + tig * 2;
                ah[mi][0] = *(uint32_t*)&sAhi[o00];
                ah[mi][1] = *(uint32_t*)&sAhi[o10];
                ah[mi][2] = *(uint32_t*)&sAhi[o00 + 8];
                ah[mi][3] = *(uint32_t*)&sAhi[o10 + 8];
                al[mi][0] = *(uint32_t*)&sAlo[o00];
                al[mi][1] = *(uint32_t*)&sAlo[o10];
                al[mi][2] = *(uint32_t*)&sAlo[o00 + 8];
                al[mi][3] = *(uint32_t*)&sAlo[o10 + 8];
            }
            #pragma unroll
            for (int ni = 0; ni < 4; ++ni) {
                int nr = wn + ni * 8 + group;
                int ob = nr * GPAD + kb + tig * 2;
                uint32_t bh0 = *(uint32_t*)&sWhi[ob];
                uint32_t bh1 = *(uint32_t*)&sWhi[ob + 8];
                uint32_t bl0 = *(uint32_t*)&sWlo[ob];
                uint32_t bl1 = *(uint32_t*)&sWlo[ob + 8];
                #pragma unroll
                for (int mi = 0; mi < 4; ++mi) {
                    mma_bf16(acc[mi][ni][0], acc[mi][ni][1],
                             acc[mi][ni][2], acc[mi][ni][3],
                             ah[mi][0], ah[mi][1], ah[mi][2], ah[mi][3],
                             bh0, bh1);
                    mma_bf16(acc[mi][ni][0], acc[mi][ni][1],
                             acc[mi][ni][2], acc[mi][ni][3],
                             ah[mi][0], ah[mi][1], ah[mi][2], ah[mi][3],
                             bl0, bl1);
                    mma_bf16(acc[mi][ni][0], acc[mi][ni][1],
                             acc[mi][ni][2], acc[mi][ni][3],
                             al[mi][0], al[mi][1], al[mi][2], al[mi][3],
                             bh0, bh1);
                }
            }
        }
        __syncthreads();
    }

    // store: c0,c1 -> (row, col..col+1); c2,c3 -> (row+8, col..col+1)
    #pragma unroll
    for (int mi = 0; mi < 4; ++mi) {
        int r0 = m0 + wm + mi * 16 + group;
        #pragma unroll
        for (int ni = 0; ni < 4; ++ni) {
            int cc = n0 + wn + ni * 8 + tig * 2;
            *(float2*)&C[(size_t)r0 * HID + cc] =
                make_float2(acc[mi][ni][0], acc[mi][ni][1]);
            *(float2*)&C[(size_t)(r0 + 8) * HID + cc] =
                make_float2(acc[mi][ni][2], acc[mi][ni][3]);
        }
    }
}

// ------------------------- flash attention (fp32 SIMT) ----------------------
struct AttnSmem {
    float Qs[64][132];
    float Ks[64][132];
    float Vs[128][68];
    float Pt[128][132];
    float rowm[128], rowl[128], alpha[128], colbias[128];
    int   qt[128], ktyp[128];
    float tb[9];
};

__global__ void __launch_bounds__(256) attn_kernel(
    const float* __restrict__ Q, const float* __restrict__ K,
    const float* __restrict__ V,
    const int* __restrict__ qtid, const int* __restrict__ ktid,
    const int* __restrict__ mask,
    const float* __restrict__ tbias,
    float* __restrict__ O) {
    extern __shared__ char smem_raw[];
    AttnSmem& s = *(AttnSmem*)smem_raw;
    int tid = threadIdx.x;
    int tx = tid & 15, ty = tid >> 4;
    int b = blockIdx.z, h = blockIdx.y, q0 = blockIdx.x * 128;

    if (tid < 128) {
        s.rowm[tid] = M_INIT;
        s.rowl[tid] = 0.f;
        s.qt[tid]   = qtid[q0 + tid];
    }
    if (tid < 9) s.tb[tid] = tbias[tid];

    #pragma unroll
    for (int l = 0; l < 8; ++l) {
        int i = tid + l * 256; int row = i >> 4; int kq = i & 15;
        float4 a = *(const float4*)(Q + (size_t)(b*NQ + q0 + row) * HID + h*HD + kq*4);
        s.Qs[kq*4+0][row] = a.x; s.Qs[kq*4+1][row] = a.y;
        s.Qs[kq*4+2][row] = a.z; s.Qs[kq*4+3][row] = a.w;
    }

    float o[8][4] = {};
    __syncthreads();
    int qtr[8];
    #pragma unroll
    for (int r = 0; r < 8; ++r) qtr[r] = s.qt[ty*8 + r];

    for (int k0 = 0; k0 < NK; k0 += 128) {
        #pragma unroll
        for (int l = 0; l < 8; ++l) {
            int i = tid + l * 256; int row = i >> 4; int kq = i & 15;
            size_t base = (size_t)(b*NK + k0 + row) * HID + h*HD + kq*4;
            float4 a = *(const float4*)(K + base);
            s.Ks[kq*4+0][row] = a.x; s.Ks[kq*4+1][row] = a.y;
            s.Ks[kq*4+2][row] = a.z; s.Ks[kq*4+3][row] = a.w;
            float4 vv = *(const float4*)(V + base);
            *(float4*)&s.Vs[row][kq*4] = vv;
        }
        if (tid < 128) {
            s.ktyp[tid]    = ktid[k0 + tid];
            s.colbias[tid] = (mask[b*NK + k0 + tid] != 0) ? 0.f : NEG_BIG;
        }
        __syncthreads();

        float sacc[8][8] = {};
        #pragma unroll 8
        for (int d = 0; d < 64; ++d) {
            float4 q0v = *(const float4*)&s.Qs[d][ty*8];
            float4 q1v = *(const float4*)&s.Qs[d][ty*8+4];
            float4 k0v = *(const float4*)&s.Ks[d][tx*8];
            float4 k1v = *(const float4*)&s.Ks[d][tx*8+4];
            float qf[8] = {q0v.x,q0v.y,q0v.z,q0v.w,q1v.x,q1v.y,q1v.z,q1v.w};
            float kf[8] = {k0v.x,k0v.y,k0v.z,k0v.w,k1v.x,k1v.y,k1v.z,k1v.w};
            #pragma unroll
            for (int r = 0; r < 8; ++r)
                #pragma unroll
                for (int c = 0; c < 8; ++c)
                    sacc[r][c] += qf[r] * kf[c];
        }
        #pragma unroll
        for (int c = 0; c < 8; ++c) {
            int j = tx*8 + c;
            float cb = s.colbias[j];
            int kty  = s.ktyp[j];
            float tmp[8];
            #pragma unroll
            for (int r = 0; r < 8; ++r)
                tmp[r] = sacc[r][c] * 0.125f + s.tb[qtr[r]*3 + kty] + cb;
            *(float4*)&s.Pt[j][ty*8]   = make_float4(tmp[0],tmp[1],tmp[2],tmp[3]);
            *(float4*)&s.Pt[j][ty*8+4] = make_float4(tmp[4],tmp[5],tmp[6],tmp[7]);
        }
        __syncthreads();

        {
            int i = tid >> 1, half = tid & 1;
            float m_old = s.rowm[i];
            float mx = M_INIT;
            #pragma unroll 8
            for (int jj = 0; jj < 64; ++jj)
                mx = fmaxf(mx, s.Pt[half*64 + jj][i]);
            mx = fmaxf(mx, __shfl_xor_sync(0xffffffffu, mx, 1));
            mx = fmaxf(mx, m_old);
            float sum = 0.f;
            #pragma unroll 8
            for (int jj = 0; jj < 64; ++jj) {
                int j = half*64 + jj;
                float p = __expf(s.Pt[j][i] - mx);
                s.Pt[j][i] = p;
                sum += p;
            }
            sum += __shfl_xor_sync(0xffffffffu, sum, 1);
            if (!half) {
                float a = __expf(m_old - mx);
                s.alpha[i] = a;
                s.rowm[i]  = mx;
                s.rowl[i]  = s.rowl[i] * a + sum;
            }
        }
        __syncthreads();

        float ar[8];
        #pragma unroll
        for (int r = 0; r < 8; ++r) ar[r] = s.alpha[ty*8 + r];
        #pragma unroll
        for (int r = 0; r < 8; ++r)
            #pragma unroll
            for (int c = 0; c < 4; ++c)
                o[r][c] *= ar[r];
        #pragma unroll 8
        for (int j = 0; j < 128; ++j) {
            float4 vf = *(const float4*)&s.Vs[j][tx*4];
            float4 p0 = *(const float4*)&s.Pt[j][ty*8];
            float4 p1 = *(const float4*)&s.Pt[j][ty*8+4];
            float pf[8] = {p0.x,p0.y,p0.z,p0.w,p1.x,p1.y,p1.z,p1.w};
            #pragma unroll
            for (int r = 0; r < 8; ++r) {
                o[r][0] += pf[r] * vf.x;
                o[r][1] += pf[r] * vf.y;
                o[r][2] += pf[r] * vf.z;
                o[r][3] += pf[r] * vf.w;
            }
        }
        __syncthreads();
    }

    #pragma unroll
    for (int r = 0; r < 8; ++r) {
        float inv = 1.0f / s.rowl[ty*8 + r];
        float4 res = make_float4(o[r][0]*inv, o[r][1]*inv, o[r][2]*inv, o[r][3]*inv);
        *(float4*)(O + (size_t)(b*NQ + q0 + ty*8 + r) * HID + h*HD + tx*4) = res;
    }
}

// ---------------------------------------------------------------------------
extern "C" void kernel_launch(void* const* d_in, const int* in_sizes, int n_in,
                              void* d_out, int out_size) {
    const float* queries = (const float*)d_in[0];
    const float* kv      = (const float*)d_in[1];
    const int*   qtid    = (const int*)d_in[2];
    const int*   ktid    = (const int*)d_in[3];
    const int*   mask    = (const int*)d_in[4];   // widened bool
    const float* Wq      = (const float*)d_in[5];
    const float* Wk      = (const float*)d_in[6];
    const float* Wv      = (const float*)d_in[7];
    const float* Wo      = (const float*)d_in[8];
    const float* qn_w    = (const float*)d_in[9];
    const float* qn_b    = (const float*)d_in[10];
    const float* kvn_w   = (const float*)d_in[11];
    const float* kvn_b   = (const float*)d_in[12];
    const float* on_w    = (const float*)d_in[13];
    const float* on_b    = (const float*)d_in[14];
    const float* tbias   = (const float*)d_in[15];
    float*       out     = (float*)d_out;

    float *q, *k, *v, *att, *proj;
    __nv_bfloat16 *qn_hi, *qn_lo, *kvn_hi, *kvn_lo, *att_hi, *att_lo, *w_hi, *w_lo;
    cudaGetSymbolAddress((void**)&q,      g_q);
    cudaGetSymbolAddress((void**)&k,      g_k);
    cudaGetSymbolAddress((void**)&v,      g_v);
    cudaGetSymbolAddress((void**)&att,    g_att);
    cudaGetSymbolAddress((void**)&proj,   g_proj);
    cudaGetSymbolAddress((void**)&qn_hi,  g_qn_hi);
    cudaGetSymbolAddress((void**)&qn_lo,  g_qn_lo);
    cudaGetSymbolAddress((void**)&kvn_hi, g_kvn_hi);
    cudaGetSymbolAddress((void**)&kvn_lo, g_kvn_lo);
    cudaGetSymbolAddress((void**)&att_hi, g_att_hi);
    cudaGetSymbolAddress((void**)&att_lo, g_att_lo);
    cudaGetSymbolAddress((void**)&w_hi,   g_w_hi);
    cudaGetSymbolAddress((void**)&w_lo,   g_w_lo);

    cudaFuncSetAttribute(attn_kernel, cudaFuncAttributeMaxDynamicSharedMemorySize,
                         (int)sizeof(AttnSmem));
    cudaFuncSetAttribute(hmma_gemm, cudaFuncAttributeMaxDynamicSharedMemorySize,
                         GEMM_SMEM);

    const int WN = HID * HID;

    // 1) LayerNorm + split-bf16 conversion of activations
    ln_cvt_kernel<<<B_ * NQ, 256>>>(queries, qn_hi, qn_lo, qn_w, qn_b);
    ln_cvt_kernel<<<B_ * NK, 256>>>(kv, kvn_hi, kvn_lo, kvn_w, kvn_b);

    // 2) weight conversion (hi/lo)
    cvt_kernel<<<WN/4/256, 256>>>(Wq, w_hi + 0*WN, w_lo + 0*WN, WN/4);
    cvt_kernel<<<WN/4/256, 256>>>(Wk, w_hi + 1*WN, w_lo + 1*WN, WN/4);
    cvt_kernel<<<WN/4/256, 256>>>(Wv, w_hi + 2*WN, w_lo + 2*WN, WN/4);
    cvt_kernel<<<WN/4/256, 256>>>(Wo, w_hi + 3*WN, w_lo + 3*WN, WN/4);

    // 3) projections (tensor cores)
    hmma_gemm<<<dim3(8, (B_*NQ)/128), 256, GEMM_SMEM>>>(
        qn_hi, qn_lo, w_hi + 0*WN, w_lo + 0*WN, q);
    hmma_gemm<<<dim3(8, (B_*NK)/128), 256, GEMM_SMEM>>>(
        kvn_hi, kvn_lo, w_hi + 1*WN, w_lo + 1*WN, k);
    hmma_gemm<<<dim3(8, (B_*NK)/128), 256, GEMM_SMEM>>>(
        kvn_hi, kvn_lo, w_hi + 2*WN, w_lo + 2*WN, v);

    // 4) attention (fp32 SIMT)
    attn_kernel<<<dim3(NQ/128, HEADS, B_), 256, sizeof(AttnSmem)>>>(
        q, k, v, qtid, ktid, mask, tbias, att);

    // 5) out projection (tensor cores)
    cvt_kernel<<<(B_*NQ*HID)/4/256, 256>>>(att, att_hi, att_lo, (B_*NQ*HID)/4);
    hmma_gemm<<<dim3(8, (B_*NQ)/128), 256, GEMM_SMEM>>>(
        att_hi, att_lo, w_hi + 3*WN, w_lo + 3*WN, proj);

    // 6) residual + LN
    addln_kernel<<<B_ * NQ, 256>>>(queries, proj, out, on_w, on_b);
}

// round 8
// speedup vs baseline: 2.1769x; 1.5055x over previous
#include <cuda_runtime.h>
#include <cuda_bf16.h>
#include <cstdint>

// ---------------------------------------------------------------------------
// SVACrossAttentionLayer on GB300.  R7: attention moved to mma.sync bf16
// (split-precision x3, register-resident flash attention).  Projections stay
// on the R6 HMMA GEMM.  B=2, Nq=1024, Nk=4096, HID=1024, H=16, hd=64.
// ---------------------------------------------------------------------------

#define B_       2
#define NQ       1024
#define NK       4096
#define HID      1024
#define HEADS    16
#define HD       64
#define LN_EPS   1e-5f
#define NEG_BIG  (-1e30f)
#define M_INIT   (-1e9f)

// ------------------------- scratch (static, no allocs) ---------------------
__device__ float         g_q    [B_ * NQ * HID];
__device__ float         g_k    [B_ * NK * HID];
__device__ float         g_v    [B_ * NK * HID];
__device__ float         g_att  [B_ * NQ * HID];
__device__ float         g_proj [B_ * NQ * HID];
__device__ __nv_bfloat16 g_qn_hi [B_ * NQ * HID];
__device__ __nv_bfloat16 g_qn_lo [B_ * NQ * HID];
__device__ __nv_bfloat16 g_kvn_hi[B_ * NK * HID];
__device__ __nv_bfloat16 g_kvn_lo[B_ * NK * HID];
__device__ __nv_bfloat16 g_att_hi[B_ * NQ * HID];
__device__ __nv_bfloat16 g_att_lo[B_ * NQ * HID];
__device__ __nv_bfloat16 g_w_hi  [4 * HID * HID];   // Wq,Wk,Wv,Wo
__device__ __nv_bfloat16 g_w_lo  [4 * HID * HID];

// ------------------------- mma.sync helper ----------------------------------
__device__ __forceinline__ void mma_bf16(
    float& c0, float& c1, float& c2, float& c3,
    uint32_t a0, uint32_t a1, uint32_t a2, uint32_t a3,
    uint32_t b0, uint32_t b1) {
    asm volatile(
        "mma.sync.aligned.m16n8k16.row.col.f32.bf16.bf16.f32 "
        "{%0,%1,%2,%3}, {%4,%5,%6,%7}, {%8,%9}, {%0,%1,%2,%3};"
        : "+f"(c0), "+f"(c1), "+f"(c2), "+f"(c3)
        : "r"(a0), "r"(a1), "r"(a2), "r"(a3), "r"(b0), "r"(b1));
}

// pack two floats -> bf16x2 reg (lo half = first arg)
__device__ __forceinline__ uint32_t pack_bf16x2(float lo, float hi) {
    uint32_t d;
    asm("cvt.rn.bf16x2.f32 %0, %1, %2;" : "=r"(d) : "f"(hi), "f"(lo));
    return d;
}
__device__ __forceinline__ uint32_t pack_bf16x2_res(float lo, float hi) {
    float lh = __bfloat162float(__float2bfloat16(lo));
    float hh = __bfloat162float(__float2bfloat16(hi));
    return pack_bf16x2(lo - lh, hi - hh);
}

// ------------------------- block reduce (256 thr) ---------------------------
__device__ __forceinline__ void block_reduce2(float& s, float& ss) {
    #pragma unroll
    for (int o = 16; o; o >>= 1) {
        s  += __shfl_xor_sync(0xffffffffu, s,  o);
        ss += __shfl_xor_sync(0xffffffffu, ss, o);
    }
    __shared__ float sh[2][8];
    int w = threadIdx.x >> 5, lane = threadIdx.x & 31;
    if (lane == 0) { sh[0][w] = s; sh[1][w] = ss; }
    __syncthreads();
    float ts = 0.f, tss = 0.f;
    #pragma unroll
    for (int k = 0; k < 8; ++k) { ts += sh[0][k]; tss += sh[1][k]; }
    s = ts; ss = tss;
    __syncthreads();
}

// ------------------------- LayerNorm -> split bf16 --------------------------
__global__ void __launch_bounds__(256) ln_cvt_kernel(
    const float* __restrict__ x,
    __nv_bfloat16* __restrict__ hi, __nv_bfloat16* __restrict__ lo,
    const float* __restrict__ w, const float* __restrict__ b) {
    int row = blockIdx.x;
    int t = threadIdx.x;
    float4 v = ((const float4*)(x + (size_t)row * HID))[t];
    float s  = v.x + v.y + v.z + v.w;
    float ss = v.x*v.x + v.y*v.y + v.z*v.z + v.w*v.w;
    block_reduce2(s, ss);
    float mean = s * (1.0f / HID);
    float var  = ss * (1.0f / HID) - mean * mean;
    float rstd = rsqrtf(var + LN_EPS);
    float4 wv = ((const float4*)w)[t], bv = ((const float4*)b)[t];
    float o0 = (v.x - mean) * rstd * wv.x + bv.x;
    float o1 = (v.y - mean) * rstd * wv.y + bv.y;
    float o2 = (v.z - mean) * rstd * wv.z + bv.z;
    float o3 = (v.w - mean) * rstd * wv.w + bv.w;
    __nv_bfloat16 h0 = __float2bfloat16(o0), h1 = __float2bfloat16(o1);
    __nv_bfloat16 h2 = __float2bfloat16(o2), h3 = __float2bfloat16(o3);
    __nv_bfloat16 l0 = __float2bfloat16(o0 - __bfloat162float(h0));
    __nv_bfloat16 l1 = __float2bfloat16(o1 - __bfloat162float(h1));
    __nv_bfloat16 l2 = __float2bfloat16(o2 - __bfloat162float(h2));
    __nv_bfloat16 l3 = __float2bfloat16(o3 - __bfloat162float(h3));
    ((ushort4*)(hi + (size_t)row * HID))[t] =
        make_ushort4(*(unsigned short*)&h0, *(unsigned short*)&h1,
                     *(unsigned short*)&h2, *(unsigned short*)&h3);
    ((ushort4*)(lo + (size_t)row * HID))[t] =
        make_ushort4(*(unsigned short*)&l0, *(unsigned short*)&l1,
                     *(unsigned short*)&l2, *(unsigned short*)&l3);
}

// ------------------------- fp32 -> split bf16 -------------------------------
__global__ void __launch_bounds__(256) cvt_kernel(
    const float* __restrict__ x,
    __nv_bfloat16* __restrict__ hi, __nv_bfloat16* __restrict__ lo, int n4) {
    int i = blockIdx.x * 256 + threadIdx.x;
    if (i >= n4) return;
    float4 v = ((const float4*)x)[i];
    __nv_bfloat16 h0 = __float2bfloat16(v.x), h1 = __float2bfloat16(v.y);
    __nv_bfloat16 h2 = __float2bfloat16(v.z), h3 = __float2bfloat16(v.w);
    __nv_bfloat16 l0 = __float2bfloat16(v.x - __bfloat162float(h0));
    __nv_bfloat16 l1 = __float2bfloat16(v.y - __bfloat162float(h1));
    __nv_bfloat16 l2 = __float2bfloat16(v.z - __bfloat162float(h2));
    __nv_bfloat16 l3 = __float2bfloat16(v.w - __bfloat162float(h3));
    ((ushort4*)hi)[i] = make_ushort4(*(unsigned short*)&h0, *(unsigned short*)&h1,
                                     *(unsigned short*)&h2, *(unsigned short*)&h3);
    ((ushort4*)lo)[i] = make_ushort4(*(unsigned short*)&l0, *(unsigned short*)&l1,
                                     *(unsigned short*)&l2, *(unsigned short*)&l3);
}

// ------------------------- residual + LayerNorm ------------------------------
__global__ void __launch_bounds__(256) addln_kernel(
    const float* __restrict__ xq, const float* __restrict__ xp,
    float* __restrict__ y,
    const float* __restrict__ w, const float* __restrict__ b) {
    int row = blockIdx.x;
    int t = threadIdx.x;
    float4 a = ((const float4*)(xq + (size_t)row * HID))[t];
    float4 c = ((const float4*)(xp + (size_t)row * HID))[t];
    float4 v;
    v.x = a.x + c.x; v.y = a.y + c.y; v.z = a.z + c.z; v.w = a.w + c.w;
    float s  = v.x + v.y + v.z + v.w;
    float ss = v.x*v.x + v.y*v.y + v.z*v.z + v.w*v.w;
    block_reduce2(s, ss);
    float mean = s * (1.0f / HID);
    float var  = ss * (1.0f / HID) - mean * mean;
    float rstd = rsqrtf(var + LN_EPS);
    float4 wv = ((const float4*)w)[t], bv = ((const float4*)b)[t], o;
    o.x = (v.x - mean) * rstd * wv.x + bv.x;
    o.y = (v.y - mean) * rstd * wv.y + bv.y;
    o.z = (v.z - mean) * rstd * wv.z + bv.z;
    o.w = (v.w - mean) * rstd * wv.w + bv.w;
    ((float4*)(y + (size_t)row * HID))[t] = o;
}

// ------------------------- HMMA GEMM (unchanged from R6) --------------------
#define GPAD 72
#define GEMM_SMEM (4 * 128 * GPAD * 2)

__global__ void __launch_bounds__(256, 2) hmma_gemm(
    const __nv_bfloat16* __restrict__ Ahi, const __nv_bfloat16* __restrict__ Alo,
    const __nv_bfloat16* __restrict__ Whi, const __nv_bfloat16* __restrict__ Wlo,
    float* __restrict__ C) {
    extern __shared__ __nv_bfloat16 smem[];
    __nv_bfloat16* sAhi = smem;
    __nv_bfloat16* sAlo = sAhi + 128 * GPAD;
    __nv_bfloat16* sWhi = sAlo + 128 * GPAD;
    __nv_bfloat16* sWlo = sWhi + 128 * GPAD;
    int tid = threadIdx.x, wid = tid >> 5, lane = tid & 31;
    int group = lane >> 2, tig = lane & 3;
    int m0 = blockIdx.y * 128, n0 = blockIdx.x * 128;
    int wm = (wid >> 2) * 64, wn = (wid & 3) * 32;

    float acc[4][4][4] = {};

    for (int kt = 0; kt < 16; ++kt) {
        #pragma unroll
        for (int l = 0; l < 4; ++l) {
            int idx = tid + l * 256;
            int row = idx >> 3, c = idx & 7;
            size_t ga = (size_t)(m0 + row) * HID + kt * 64 + c * 8;
            size_t gw = (size_t)(n0 + row) * HID + kt * 64 + c * 8;
            *(uint4*)&sAhi[row * GPAD + c * 8] = *(const uint4*)&Ahi[ga];
            *(uint4*)&sAlo[row * GPAD + c * 8] = *(const uint4*)&Alo[ga];
            *(uint4*)&sWhi[row * GPAD + c * 8] = *(const uint4*)&Whi[gw];
            *(uint4*)&sWlo[row * GPAD + c * 8] = *(const uint4*)&Wlo[gw];
        }
        __syncthreads();

        #pragma unroll
        for (int ks = 0; ks < 4; ++ks) {
            int kb = ks * 16;
            uint32_t ah[4][4], al[4][4];
            #pragma unroll
            for (int mi = 0; mi < 4; ++mi) {
                int r0 = wm + mi * 16 + group;
                int o00 = r0 * GPAD + kb + tig * 2;
                int o10 = (r0 + 8) * GPAD + kb + tig * 2;
                ah[mi][0] = *(uint32_t*)&sAhi[o00];
                ah[mi][1] = *(uint32_t*)&sAhi[o10];
                ah[mi][2] = *(uint32_t*)&sAhi[o00 + 8];
                ah[mi][3] = *(uint32_t*)&sAhi[o10 + 8];
                al[mi][0] = *(uint32_t*)&sAlo[o00];
                al[mi][1] = *(uint32_t*)&sAlo[o10];
                al[mi][2] = *(uint32_t*)&sAlo[o00 + 8];
                al[mi][3] = *(uint32_t*)&sAlo[o10 + 8];
            }
            #pragma unroll
            for (int ni = 0; ni < 4; ++ni) {
                int nr = wn + ni * 8 + group;
                int ob = nr * GPAD + kb + tig * 2;
                uint32_t bh0 = *(uint32_t*)&sWhi[ob];
                uint32_t bh1 = *(uint32_t*)&sWhi[ob + 8];
                uint32_t bl0 = *(uint32_t*)&sWlo[ob];
                uint32_t bl1 = *(uint32_t*)&sWlo[ob + 8];
                #pragma unroll
                for (int mi = 0; mi < 4; ++mi) {
                    mma_bf16(acc[mi][ni][0], acc[mi][ni][1],
                             acc[mi][ni][2], acc[mi][ni][3],
                             ah[mi][0], ah[mi][1], ah[mi][2], ah[mi][3],
                             bh0, bh1);
                    mma_bf16(acc[mi][ni][0], acc[mi][ni][1],
                             acc[mi][ni][2], acc[mi][ni][3],
                             ah[mi][0], ah[mi][1], ah[mi][2], ah[mi][3],
                             bl0, bl1);
                    mma_bf16(acc[mi][ni][0], acc[mi][ni][1],
                             acc[mi][ni][2], acc[mi][ni][3],
                             al[mi][0], al[mi][1], al[mi][2], al[mi][3],
                             bh0, bh1);
                }
            }
        }
        __syncthreads();
    }

    #pragma unroll
    for (int mi = 0; mi < 4; ++mi) {
        int r0 = m0 + wm + mi * 16 + group;
        #pragma unroll
        for (int ni = 0; ni < 4; ++ni) {
            int cc = n0 + wn + ni * 8 + tig * 2;
            *(float2*)&C[(size_t)r0 * HID + cc] =
                make_float2(acc[mi][ni][0], acc[mi][ni][1]);
            *(float2*)&C[(size_t)(r0 + 8) * HID + cc] =
                make_float2(acc[mi][ni][2], acc[mi][ni][3]);
        }
    }
}

// ------------------------- HMMA flash attention ------------------------------
// Block: 128 q x (head, batch); k-tiles of 128.  8 warps, warp = 16 q rows.
// S and PV both split-precision (hi*hi + hi*lo + lo*hi) on tensor cores.
// Softmax is register-resident (quad shfl reductions).
#define APAD 72      // Q/K smem row pad (bf16): conflict-free fragment LDS
#define VPAD 136     // Vt smem row pad
#define ATT_SQ   (128 * APAD)
#define ATT_SV   (64 * VPAD)
#define ATT_SMEM (6 * ATT_SQ * 0 + (4 * ATT_SQ + 2 * ATT_SV) * 2 + 512 + 512 + 64)

__device__ __forceinline__ void split_store4(
    __nv_bfloat16* hi, __nv_bfloat16* lo, int off, float4 v) {
    __nv_bfloat16 h0 = __float2bfloat16(v.x), h1 = __float2bfloat16(v.y);
    __nv_bfloat16 h2 = __float2bfloat16(v.z), h3 = __float2bfloat16(v.w);
    __nv_bfloat16 l0 = __float2bfloat16(v.x - __bfloat162float(h0));
    __nv_bfloat16 l1 = __float2bfloat16(v.y - __bfloat162float(h1));
    __nv_bfloat16 l2 = __float2bfloat16(v.z - __bfloat162float(h2));
    __nv_bfloat16 l3 = __float2bfloat16(v.w - __bfloat162float(h3));
    *(ushort4*)&hi[off] = make_ushort4(*(unsigned short*)&h0, *(unsigned short*)&h1,
                                       *(unsigned short*)&h2, *(unsigned short*)&h3);
    *(ushort4*)&lo[off] = make_ushort4(*(unsigned short*)&l0, *(unsigned short*)&l1,
                                       *(unsigned short*)&l2, *(unsigned short*)&l3);
}

__global__ void __launch_bounds__(256) attn_hmma(
    const float* __restrict__ Q, const float* __restrict__ K,
    const float* __restrict__ V,
    const int* __restrict__ qtid, const int* __restrict__ ktid,
    const int* __restrict__ mask,
    const float* __restrict__ tbias,
    float* __restrict__ O) {
    extern __shared__ char sm[];
    __nv_bfloat16* Qhi  = (__nv_bfloat16*)sm;
    __nv_bfloat16* Qlo  = Qhi + ATT_SQ;
    __nv_bfloat16* Khi  = Qlo + ATT_SQ;
    __nv_bfloat16* Klo  = Khi + ATT_SQ;
    __nv_bfloat16* Vthi = Klo + ATT_SQ;
    __nv_bfloat16* Vtlo = Vthi + ATT_SV;
    float* sCb = (float*)(Vtlo + ATT_SV);
    int*   sKt = (int*)(sCb + 128);
    float* sTb = (float*)(sKt + 128);

    int tid = threadIdx.x, w = tid >> 5, lane = tid & 31;
    int group = lane >> 2, tig = lane & 3;
    int b = blockIdx.z, h = blockIdx.y, q0 = blockIdx.x * 128;

    // Q tile (fp32 -> split bf16), row-major k-contiguous
    #pragma unroll
    for (int l = 0; l < 8; ++l) {
        int idx = tid + l * 256;              // 0..2047
        int row = idx >> 4, ch = idx & 15;    // 16 chunks of 4 floats
        float4 v = *(const float4*)(Q + (size_t)(b*NQ + q0 + row) * HID + h*HD + ch*4);
        split_store4(Qhi, Qlo, row * APAD + ch * 4, v);
    }
    if (tid < 9) sTb[tid] = tbias[tid];
    __syncthreads();

    int qt0 = qtid[q0 + w*16 + group];
    int qt1 = qtid[q0 + w*16 + group + 8];
    float t00 = sTb[qt0*3+0], t01 = sTb[qt0*3+1], t02 = sTb[qt0*3+2];
    float t10 = sTb[qt1*3+0], t11 = sTb[qt1*3+1], t12 = sTb[qt1*3+2];

    float m0 = M_INIT, m1 = M_INIT, l0 = 0.f, l1 = 0.f;
    float oacc[8][4] = {};

    for (int kv0 = 0; kv0 < NK; kv0 += 128) {
        // K tile -> split bf16 (row-major, k-contiguous)
        #pragma unroll
        for (int l = 0; l < 8; ++l) {
            int idx = tid + l * 256;
            int row = idx >> 4, ch = idx & 15;
            float4 v = *(const float4*)(K + (size_t)(b*NK + kv0 + row) * HID + h*HD + ch*4);
            split_store4(Khi, Klo, row * APAD + ch * 4, v);
        }
        // V tile -> transposed split bf16 Vt[d][j]
        #pragma unroll
        for (int l = 0; l < 8; ++l) {
            int idx = tid + l * 256;
            int j = idx & 127, dch = idx >> 7;     // dch 0..15
            float4 v = *(const float4*)(V + (size_t)(b*NK + kv0 + j) * HID + h*HD + dch*4);
            float vals[4] = {v.x, v.y, v.z, v.w};
            #pragma unroll
            for (int e = 0; e < 4; ++e) {
                __nv_bfloat16 hh = __float2bfloat16(vals[e]);
                Vthi[(dch*4 + e) * VPAD + j] = hh;
                Vtlo[(dch*4 + e) * VPAD + j] =
                    __float2bfloat16(vals[e] - __bfloat162float(hh));
            }
        }
        if (tid < 128) {
            sKt[tid] = ktid[kv0 + tid];
            sCb[tid] = (mask[b*NK + kv0 + tid] != 0) ? 0.f : NEG_BIG;
        }
        __syncthreads();

        // ---- S = Q @ K^T (split x3) ----
        float sacc[16][4] = {};
        #pragma unroll
        for (int kc = 0; kc < 4; ++kc) {
            int ro = (w*16 + group) * APAD + kc*16 + tig*2;
            uint32_t ah0 = *(uint32_t*)&Qhi[ro];
            uint32_t ah1 = *(uint32_t*)&Qhi[ro + 8*APAD];
            uint32_t ah2 = *(uint32_t*)&Qhi[ro + 8];
            uint32_t ah3 = *(uint32_t*)&Qhi[ro + 8*APAD + 8];
            uint32_t al0 = *(uint32_t*)&Qlo[ro];
            uint32_t al1 = *(uint32_t*)&Qlo[ro + 8*APAD];
            uint32_t al2 = *(uint32_t*)&Qlo[ro + 8];
            uint32_t al3 = *(uint32_t*)&Qlo[ro + 8*APAD + 8];
            #pragma unroll
            for (int ni = 0; ni < 16; ++ni) {
                int bo = (ni*8 + group) * APAD + kc*16 + tig*2;
                uint32_t bh0 = *(uint32_t*)&Khi[bo];
                uint32_t bh1 = *(uint32_t*)&Khi[bo + 8];
                uint32_t bl0 = *(uint32_t*)&Klo[bo];
                uint32_t bl1 = *(uint32_t*)&Klo[bo + 8];
                mma_bf16(sacc[ni][0], sacc[ni][1], sacc[ni][2], sacc[ni][3],
                         ah0, ah1, ah2, ah3, bh0, bh1);
                mma_bf16(sacc[ni][0], sacc[ni][1], sacc[ni][2], sacc[ni][3],
                         ah0, ah1, ah2, ah3, bl0, bl1);
                mma_bf16(sacc[ni][0], sacc[ni][1], sacc[ni][2], sacc[ni][3],
                         al0, al1, al2, al3, bh0, bh1);
            }
        }

        // ---- epilogue: scale + typed bias + mask; row max ----
        float mx0 = -3.0e38f, mx1 = -3.0e38f;
        #pragma unroll
        for (int ni = 0; ni < 16; ++ni) {
            int j0 = ni*8 + tig*2;
            float cb0 = sCb[j0], cb1 = sCb[j0+1];
            int kt0 = sKt[j0], kt1 = sKt[j0+1];
            float b00 = (kt0 == 0 ? t00 : kt0 == 1 ? t01 : t02) + cb0;
            float b01 = (kt1 == 0 ? t00 : kt1 == 1 ? t01 : t02) + cb1;
            float b10 = (kt0 == 0 ? t10 : kt0 == 1 ? t11 : t12) + cb0;
            float b11 = (kt1 == 0 ? t10 : kt1 == 1 ? t11 : t12) + cb1;
            sacc[ni][0] = sacc[ni][0] * 0.125f + b00;
            sacc[ni][1] = sacc[ni][1] * 0.125f + b01;
            sacc[ni][2] = sacc[ni][2] * 0.125f + b10;
            sacc[ni][3] = sacc[ni][3] * 0.125f + b11;
            mx0 = fmaxf(mx0, fmaxf(sacc[ni][0], sacc[ni][1]));
            mx1 = fmaxf(mx1, fmaxf(sacc[ni][2], sacc[ni][3]));
        }
        mx0 = fmaxf(mx0, __shfl_xor_sync(0xffffffffu, mx0, 1));
        mx0 = fmaxf(mx0, __shfl_xor_sync(0xffffffffu, mx0, 2));
        mx1 = fmaxf(mx1, __shfl_xor_sync(0xffffffffu, mx1, 1));
        mx1 = fmaxf(mx1, __shfl_xor_sync(0xffffffffu, mx1, 2));

        float mn0 = fmaxf(m0, mx0), mn1 = fmaxf(m1, mx1);
        float al_0 = __expf(m0 - mn0), al_1 = __expf(m1 - mn1);
        m0 = mn0; m1 = mn1;

        float sum0 = 0.f, sum1 = 0.f;
        #pragma unroll
        for (int ni = 0; ni < 16; ++ni) {
            float p0 = __expf(sacc[ni][0] - mn0);
            float p1 = __expf(sacc[ni][1] - mn0);
            float p2 = __expf(sacc[ni][2] - mn1);
            float p3 = __expf(sacc[ni][3] - mn1);
            sacc[ni][0] = p0; sacc[ni][1] = p1;
            sacc[ni][2] = p2; sacc[ni][3] = p3;
            sum0 += p0 + p1; sum1 += p2 + p3;
        }
        sum0 += __shfl_xor_sync(0xffffffffu, sum0, 1);
        sum0 += __shfl_xor_sync(0xffffffffu, sum0, 2);
        sum1 += __shfl_xor_sync(0xffffffffu, sum1, 1);
        sum1 += __shfl_xor_sync(0xffffffffu, sum1, 2);
        l0 = l0 * al_0 + sum0;
        l1 = l1 * al_1 + sum1;

        #pragma unroll
        for (int nd = 0; nd < 8; ++nd) {
            oacc[nd][0] *= al_0; oacc[nd][1] *= al_0;
            oacc[nd][2] *= al_1; oacc[nd][3] *= al_1;
        }

        // ---- O += P @ V (split x3), P straight from registers ----
        #pragma unroll
        for (int kk = 0; kk < 8; ++kk) {
            uint32_t ph0 = pack_bf16x2(sacc[2*kk][0],   sacc[2*kk][1]);
            uint32_t ph1 = pack_bf16x2(sacc[2*kk][2],   sacc[2*kk][3]);
            uint32_t ph2 = pack_bf16x2(sacc[2*kk+1][0], sacc[2*kk+1][1]);
            uint32_t ph3 = pack_bf16x2(sacc[2*kk+1][2], sacc[2*kk+1][3]);
            uint32_t pl0 = pack_bf16x2_res(sacc[2*kk][0],   sacc[2*kk][1]);
            uint32_t pl1 = pack_bf16x2_res(sacc[2*kk][2],   sacc[2*kk][3]);
            uint32_t pl2 = pack_bf16x2_res(sacc[2*kk+1][0], sacc[2*kk+1][1]);
            uint32_t pl3 = pack_bf16x2_res(sacc[2*kk+1][2], sacc[2*kk+1][3]);
            #pragma unroll
            for (int nd = 0; nd < 8; ++nd) {
                int bo = (nd*8 + group) * VPAD + kk*16 + tig*2;
                uint32_t bh0 = *(uint32_t*)&Vthi[bo];
                uint32_t bh1 = *(uint32_t*)&Vthi[bo + 8];
                uint32_t bl0 = *(uint32_t*)&Vtlo[bo];
                uint32_t bl1 = *(uint32_t*)&Vtlo[bo + 8];
                mma_bf16(oacc[nd][0], oacc[nd][1], oacc[nd][2], oacc[nd][3],
                         ph0, ph1, ph2, ph3, bh0, bh1);
                mma_bf16(oacc[nd][0], oacc[nd][1], oacc[nd][2], oacc[nd][3],
                         ph0, ph1, ph2, ph3, bl0, bl1);
                mma_bf16(oacc[nd][0], oacc[nd][1], oacc[nd][2], oacc[nd][3],
                         pl0, pl1, pl2, pl3, bh0, bh1);
            }
        }
        __syncthreads();
    }

    float inv0 = 1.0f / l0, inv1 = 1.0f / l1;
    int r0 = b*NQ + q0 + w*16 + group;
    #pragma unroll
    for (int nd = 0; nd < 8; ++nd) {
        int cc = h*HD + nd*8 + tig*2;
        *(float2*)&O[(size_t)r0 * HID + cc] =
            make_float2(oacc[nd][0] * inv0, oacc[nd][1] * inv0);
        *(float2*)&O[(size_t)(r0 + 8) * HID + cc] =
            make_float2(oacc[nd][2] * inv1, oacc[nd][3] * inv1);
    }
}

#define ATT_SMEM_BYTES ((4 * ATT_SQ + 2 * ATT_SV) * 2 + 512 + 512 + 64)

// ---------------------------------------------------------------------------
extern "C" void kernel_launch(void* const* d_in, const int* in_sizes, int n_in,
                              void* d_out, int out_size) {
    const float* queries = (const float*)d_in[0];
    const float* kv      = (const float*)d_in[1];
    const int*   qtid    = (const int*)d_in[2];
    const int*   ktid    = (const int*)d_in[3];
    const int*   mask    = (const int*)d_in[4];   // widened bool
    const float* Wq      = (const float*)d_in[5];
    const float* Wk      = (const float*)d_in[6];
    const float* Wv      = (const float*)d_in[7];
    const float* Wo      = (const float*)d_in[8];
    const float* qn_w    = (const float*)d_in[9];
    const float* qn_b    = (const float*)d_in[10];
    const float* kvn_w   = (const float*)d_in[11];
    const float* kvn_b   = (const float*)d_in[12];
    const float* on_w    = (const float*)d_in[13];
    const float* on_b    = (const float*)d_in[14];
    const float* tbias   = (const float*)d_in[15];
    float*       out     = (float*)d_out;

    float *q, *k, *v, *att, *proj;
    __nv_bfloat16 *qn_hi, *qn_lo, *kvn_hi, *kvn_lo, *att_hi, *att_lo, *w_hi, *w_lo;
    cudaGetSymbolAddress((void**)&q,      g_q);
    cudaGetSymbolAddress((void**)&k,      g_k);
    cudaGetSymbolAddress((void**)&v,      g_v);
    cudaGetSymbolAddress((void**)&att,    g_att);
    cudaGetSymbolAddress((void**)&proj,   g_proj);
    cudaGetSymbolAddress((void**)&qn_hi,  g_qn_hi);
    cudaGetSymbolAddress((void**)&qn_lo,  g_qn_lo);
    cudaGetSymbolAddress((void**)&kvn_hi, g_kvn_hi);
    cudaGetSymbolAddress((void**)&kvn_lo, g_kvn_lo);
    cudaGetSymbolAddress((void**)&att_hi, g_att_hi);
    cudaGetSymbolAddress((void**)&att_lo, g_att_lo);
    cudaGetSymbolAddress((void**)&w_hi,   g_w_hi);
    cudaGetSymbolAddress((void**)&w_lo,   g_w_lo);

    cudaFuncSetAttribute(hmma_gemm, cudaFuncAttributeMaxDynamicSharedMemorySize,
                         GEMM_SMEM);
    cudaFuncSetAttribute(attn_hmma, cudaFuncAttributeMaxDynamicSharedMemorySize,
                         ATT_SMEM_BYTES);

    const int WN = HID * HID;

    // 1) LayerNorm + split-bf16 conversion of activations
    ln_cvt_kernel<<<B_ * NQ, 256>>>(queries, qn_hi, qn_lo, qn_w, qn_b);
    ln_cvt_kernel<<<B_ * NK, 256>>>(kv, kvn_hi, kvn_lo, kvn_w, kvn_b);

    // 2) weight conversion (hi/lo)
    cvt_kernel<<<WN/4/256, 256>>>(Wq, w_hi + 0*WN, w_lo + 0*WN, WN/4);
    cvt_kernel<<<WN/4/256, 256>>>(Wk, w_hi + 1*WN, w_lo + 1*WN, WN/4);
    cvt_kernel<<<WN/4/256, 256>>>(Wv, w_hi + 2*WN, w_lo + 2*WN, WN/4);
    cvt_kernel<<<WN/4/256, 256>>>(Wo, w_hi + 3*WN, w_lo + 3*WN, WN/4);

    // 3) projections (tensor cores)
    hmma_gemm<<<dim3(8, (B_*NQ)/128), 256, GEMM_SMEM>>>(
        qn_hi, qn_lo, w_hi + 0*WN, w_lo + 0*WN, q);
    hmma_gemm<<<dim3(8, (B_*NK)/128), 256, GEMM_SMEM>>>(
        kvn_hi, kvn_lo, w_hi + 1*WN, w_lo + 1*WN, k);
    hmma_gemm<<<dim3(8, (B_*NK)/128), 256, GEMM_SMEM>>>(
        kvn_hi, kvn_lo, w_hi + 2*WN, w_lo + 2*WN, v);

    // 4) attention (tensor cores, register-resident softmax)
    attn_hmma<<<dim3(NQ/128, HEADS, B_), 256, ATT_SMEM_BYTES>>>(
        q, k, v, qtid, ktid, mask, tbias, att);

    // 5) out projection (tensor cores)
    cvt_kernel<<<(B_*NQ*HID)/4/256, 256>>>(att, att_hi, att_lo, (B_*NQ*HID)/4);
    hmma_gemm<<<dim3(8, (B_*NQ)/128), 256, GEMM_SMEM>>>(
        att_hi, att_lo, w_hi + 3*WN, w_lo + 3*WN, proj);

    // 6) residual + LN
    addln_kernel<<<B_ * NQ, 256>>>(queries, proj, out, on_w, on_b);
}

// round 9
// speedup vs baseline: 2.3096x; 1.0610x over previous
#include <cuda_runtime.h>
#include <cuda_bf16.h>
#include <cstdint>

// ---------------------------------------------------------------------------
// SVACrossAttentionLayer on GB300.  R8: K/V/Q pre-split to bf16 hi/lo in GEMM
// epilogue; attention uses cp.async double-buffered pipelines and
// ldmatrix.x4.trans for V fragments (no transpose stores, no convert math).
// B=2, Nq=1024, Nk=4096, HID=1024, H=16, hd=64.
// ---------------------------------------------------------------------------

#define B_       2
#define NQ       1024
#define NK       4096
#define HID      1024
#define HEADS    16
#define HD       64
#define LN_EPS   1e-5f
#define NEG_BIG  (-1e30f)
#define M_INIT   (-1e9f)

// ------------------------- scratch (static, no allocs) ---------------------
__device__ float         g_proj [B_ * NQ * HID];
__device__ __nv_bfloat16 g_qn_hi [B_ * NQ * HID];
__device__ __nv_bfloat16 g_qn_lo [B_ * NQ * HID];
__device__ __nv_bfloat16 g_kvn_hi[B_ * NK * HID];
__device__ __nv_bfloat16 g_kvn_lo[B_ * NK * HID];
__device__ __nv_bfloat16 g_q_hi [B_ * NQ * HID];
__device__ __nv_bfloat16 g_q_lo [B_ * NQ * HID];
__device__ __nv_bfloat16 g_k_hi [B_ * NK * HID];
__device__ __nv_bfloat16 g_k_lo [B_ * NK * HID];
__device__ __nv_bfloat16 g_v_hi [B_ * NK * HID];
__device__ __nv_bfloat16 g_v_lo [B_ * NK * HID];
__device__ __nv_bfloat16 g_att_hi[B_ * NQ * HID];
__device__ __nv_bfloat16 g_att_lo[B_ * NQ * HID];
__device__ __nv_bfloat16 g_w_hi  [4 * HID * HID];   // Wq,Wk,Wv,Wo
__device__ __nv_bfloat16 g_w_lo  [4 * HID * HID];

// ------------------------- PTX helpers --------------------------------------
__device__ __forceinline__ void mma_bf16(
    float& c0, float& c1, float& c2, float& c3,
    uint32_t a0, uint32_t a1, uint32_t a2, uint32_t a3,
    uint32_t b0, uint32_t b1) {
    asm volatile(
        "mma.sync.aligned.m16n8k16.row.col.f32.bf16.bf16.f32 "
        "{%0,%1,%2,%3}, {%4,%5,%6,%7}, {%8,%9}, {%0,%1,%2,%3};"
        : "+f"(c0), "+f"(c1), "+f"(c2), "+f"(c3)
        : "r"(a0), "r"(a1), "r"(a2), "r"(a3), "r"(b0), "r"(b1));
}
__device__ __forceinline__ void ldsm_x4_trans(
    uint32_t& r0, uint32_t& r1, uint32_t& r2, uint32_t& r3, uint32_t addr) {
    asm volatile("ldmatrix.sync.aligned.m8n8.x4.trans.shared.b16 {%0,%1,%2,%3}, [%4];"
                 : "=r"(r0), "=r"(r1), "=r"(r2), "=r"(r3) : "r"(addr));
}
__device__ __forceinline__ uint32_t smem_u32(const void* p) {
    uint32_t a;
    asm("{ .reg .u64 t; cvta.to.shared.u64 t, %1; cvt.u32.u64 %0, t; }"
        : "=r"(a) : "l"(p));
    return a;
}
__device__ __forceinline__ void cpa16(uint32_t dst, const void* src) {
    asm volatile("cp.async.cg.shared.global [%0], [%1], 16;" :: "r"(dst), "l"(src));
}
#define CP_COMMIT() asm volatile("cp.async.commit_group;" ::: "memory")
#define CP_WAIT0()  asm volatile("cp.async.wait_group 0;" ::: "memory")
#define CP_WAIT1()  asm volatile("cp.async.wait_group 1;" ::: "memory")

__device__ __forceinline__ uint32_t pack_bf16x2(float lo, float hi) {
    uint32_t d;
    asm("cvt.rn.bf16x2.f32 %0, %1, %2;" : "=r"(d) : "f"(hi), "f"(lo));
    return d;
}
__device__ __forceinline__ uint32_t pack_bf16x2_res(float lo, float hi) {
    float lh = __bfloat162float(__float2bfloat16(lo));
    float hh = __bfloat162float(__float2bfloat16(hi));
    return pack_bf16x2(lo - lh, hi - hh);
}
__device__ __forceinline__ void store_split2(
    __nv_bfloat16* hi, __nv_bfloat16* lo, size_t off, float a, float b) {
    __nv_bfloat16 h0 = __float2bfloat16(a), h1 = __float2bfloat16(b);
    __nv_bfloat16 l0 = __float2bfloat16(a - __bfloat162float(h0));
    __nv_bfloat16 l1 = __float2bfloat16(b - __bfloat162float(h1));
    *(ushort2*)&hi[off] = make_ushort2(*(unsigned short*)&h0, *(unsigned short*)&h1);
    *(ushort2*)&lo[off] = make_ushort2(*(unsigned short*)&l0, *(unsigned short*)&l1);
}

// ------------------------- block reduce (256 thr) ---------------------------
__device__ __forceinline__ void block_reduce2(float& s, float& ss) {
    #pragma unroll
    for (int o = 16; o; o >>= 1) {
        s  += __shfl_xor_sync(0xffffffffu, s,  o);
        ss += __shfl_xor_sync(0xffffffffu, ss, o);
    }
    __shared__ float sh[2][8];
    int w = threadIdx.x >> 5, lane = threadIdx.x & 31;
    if (lane == 0) { sh[0][w] = s; sh[1][w] = ss; }
    __syncthreads();
    float ts = 0.f, tss = 0.f;
    #pragma unroll
    for (int k = 0; k < 8; ++k) { ts += sh[0][k]; tss += sh[1][k]; }
    s = ts; ss = tss;
    __syncthreads();
}

// ------------------------- LayerNorm -> split bf16 --------------------------
__global__ void __launch_bounds__(256) ln_cvt_kernel(
    const float* __restrict__ x,
    __nv_bfloat16* __restrict__ hi, __nv_bfloat16* __restrict__ lo,
    const float* __restrict__ w, const float* __restrict__ b) {
    int row = blockIdx.x;
    int t = threadIdx.x;
    float4 v = ((const float4*)(x + (size_t)row * HID))[t];
    float s  = v.x + v.y + v.z + v.w;
    float ss = v.x*v.x + v.y*v.y + v.z*v.z + v.w*v.w;
    block_reduce2(s, ss);
    float mean = s * (1.0f / HID);
    float var  = ss * (1.0f / HID) - mean * mean;
    float rstd = rsqrtf(var + LN_EPS);
    float4 wv = ((const float4*)w)[t], bv = ((const float4*)b)[t];
    float o0 = (v.x - mean) * rstd * wv.x + bv.x;
    float o1 = (v.y - mean) * rstd * wv.y + bv.y;
    float o2 = (v.z - mean) * rstd * wv.z + bv.z;
    float o3 = (v.w - mean) * rstd * wv.w + bv.w;
    store_split2(hi, lo, (size_t)row * HID + t*4,     o0, o1);
    store_split2(hi, lo, (size_t)row * HID + t*4 + 2, o2, o3);
}

// ------------------------- fp32 -> split bf16 (weights) ---------------------
__global__ void __launch_bounds__(256) cvt_kernel(
    const float* __restrict__ x,
    __nv_bfloat16* __restrict__ hi, __nv_bfloat16* __restrict__ lo, int n4) {
    int i = blockIdx.x * 256 + threadIdx.x;
    if (i >= n4) return;
    float4 v = ((const float4*)x)[i];
    store_split2(hi, lo, (size_t)i*4,     v.x, v.y);
    store_split2(hi, lo, (size_t)i*4 + 2, v.z, v.w);
}

// ------------------------- residual + LayerNorm ------------------------------
__global__ void __launch_bounds__(256) addln_kernel(
    const float* __restrict__ xq, const float* __restrict__ xp,
    float* __restrict__ y,
    const float* __restrict__ w, const float* __restrict__ b) {
    int row = blockIdx.x;
    int t = threadIdx.x;
    float4 a = ((const float4*)(xq + (size_t)row * HID))[t];
    float4 c = ((const float4*)(xp + (size_t)row * HID))[t];
    float4 v;
    v.x = a.x + c.x; v.y = a.y + c.y; v.z = a.z + c.z; v.w = a.w + c.w;
    float s  = v.x + v.y + v.z + v.w;
    float ss = v.x*v.x + v.y*v.y + v.z*v.z + v.w*v.w;
    block_reduce2(s, ss);
    float mean = s * (1.0f / HID);
    float var  = ss * (1.0f / HID) - mean * mean;
    float rstd = rsqrtf(var + LN_EPS);
    float4 wv = ((const float4*)w)[t], bv = ((const float4*)b)[t], o;
    o.x = (v.x - mean) * rstd * wv.x + bv.x;
    o.y = (v.y - mean) * rstd * wv.y + bv.y;
    o.z = (v.z - mean) * rstd * wv.z + bv.z;
    o.w = (v.w - mean) * rstd * wv.w + bv.w;
    ((float4*)(y + (size_t)row * HID))[t] = o;
}

// ------------------------- HMMA GEMM core (macro-shared) --------------------
#define GPAD 72
#define GEMM_SMEM (4 * 128 * GPAD * 2)

#define GEMM_BODY(EPILOGUE)                                                   \
    extern __shared__ __nv_bfloat16 smem[];                                   \
    __nv_bfloat16* sAhi = smem;                                               \
    __nv_bfloat16* sAlo = sAhi + 128 * GPAD;                                  \
    __nv_bfloat16* sWhi = sAlo + 128 * GPAD;                                  \
    __nv_bfloat16* sWlo = sWhi + 128 * GPAD;                                  \
    int tid = threadIdx.x, wid = tid >> 5, lane = tid & 31;                   \
    int group = lane >> 2, tig = lane & 3;                                    \
    int m0 = blockIdx.y * 128, n0 = blockIdx.x * 128;                         \
    int wm = (wid >> 2) * 64, wn = (wid & 3) * 32;                            \
    float acc[4][4][4] = {};                                                  \
    for (int kt = 0; kt < 16; ++kt) {                                         \
        _Pragma("unroll")                                                     \
        for (int l = 0; l < 4; ++l) {                                         \
            int idx = tid + l * 256;                                          \
            int row = idx >> 3, c = idx & 7;                                  \
            size_t ga = (size_t)(m0 + row) * HID + kt * 64 + c * 8;           \
            size_t gw = (size_t)(n0 + row) * HID + kt * 64 + c * 8;           \
            *(uint4*)&sAhi[row * GPAD + c * 8] = *(const uint4*)&Ahi[ga];     \
            *(uint4*)&sAlo[row * GPAD + c * 8] = *(const uint4*)&Alo[ga];     \
            *(uint4*)&sWhi[row * GPAD + c * 8] = *(const uint4*)&Whi[gw];     \
            *(uint4*)&sWlo[row * GPAD + c * 8] = *(const uint4*)&Wlo[gw];     \
        }                                                                     \
        __syncthreads();                                                      \
        _Pragma("unroll")                                                     \
        for (int ks = 0; ks < 4; ++ks) {                                      \
            int kb = ks * 16;                                                 \
            uint32_t ah[4][4], al[4][4];                                      \
            _Pragma("unroll")                                                 \
            for (int mi = 0; mi < 4; ++mi) {                                  \
                int r0 = wm + mi * 16 + group;                                \
                int o00 = r0 * GPAD + kb + tig * 2;                           \
                int o10 = (r0 + 8) * GPAD + kb + tig * 2;                     \
                ah[mi][0] = *(uint32_t*)&sAhi[o00];                           \
                ah[mi][1] = *(uint32_t*)&sAhi[o10];                           \
                ah[mi][2] = *(uint32_t*)&sAhi[o00 + 8];                       \
                ah[mi][3] = *(uint32_t*)&sAhi[o10 + 8];                       \
                al[mi][0] = *(uint32_t*)&sAlo[o00];                           \
                al[mi][1] = *(uint32_t*)&sAlo[o10];                           \
                al[mi][2] = *(uint32_t*)&sAlo[o00 + 8];                       \
                al[mi][3] = *(uint32_t*)&sAlo[o10 + 8];                       \
            }                                                                 \
            _Pragma("unroll")                                                 \
            for (int ni = 0; ni < 4; ++ni) {                                  \
                int nr = wn + ni * 8 + group;                                 \
                int ob = nr * GPAD + kb + tig * 2;                            \
                uint32_t bh0 = *(uint32_t*)&sWhi[ob];                         \
                uint32_t bh1 = *(uint32_t*)&sWhi[ob + 8];                     \
                uint32_t bl0 = *(uint32_t*)&sWlo[ob];                         \
                uint32_t bl1 = *(uint32_t*)&sWlo[ob + 8];                     \
                _Pragma("unroll")                                             \
                for (int mi = 0; mi < 4; ++mi) {                              \
                    mma_bf16(acc[mi][ni][0], acc[mi][ni][1],                  \
                             acc[mi][ni][2], acc[mi][ni][3],                  \
                             ah[mi][0], ah[mi][1], ah[mi][2], ah[mi][3],      \
                             bh0, bh1);                                       \
                    mma_bf16(acc[mi][ni][0], acc[mi][ni][1],                  \
                             acc[mi][ni][2], acc[mi][ni][3],                  \
                             ah[mi][0], ah[mi][1], ah[mi][2], ah[mi][3],      \
                             bl0, bl1);                                       \
                    mma_bf16(acc[mi][ni][0], acc[mi][ni][1],                  \
                             acc[mi][ni][2], acc[mi][ni][3],                  \
                             al[mi][0], al[mi][1], al[mi][2], al[mi][3],      \
                             bh0, bh1);                                       \
                }                                                             \
            }                                                                 \
        }                                                                     \
        __syncthreads();                                                      \
    }                                                                         \
    EPILOGUE

__global__ void __launch_bounds__(256, 2) hmma_gemm_f32(
    const __nv_bfloat16* __restrict__ Ahi, const __nv_bfloat16* __restrict__ Alo,
    const __nv_bfloat16* __restrict__ Whi, const __nv_bfloat16* __restrict__ Wlo,
    float* __restrict__ C) {
    GEMM_BODY(
        _Pragma("unroll")
        for (int mi = 0; mi < 4; ++mi) {
            int r0 = m0 + wm + mi * 16 + group;
            _Pragma("unroll")
            for (int ni = 0; ni < 4; ++ni) {
                int cc = n0 + wn + ni * 8 + tig * 2;
                *(float2*)&C[(size_t)r0 * HID + cc] =
                    make_float2(acc[mi][ni][0], acc[mi][ni][1]);
                *(float2*)&C[(size_t)(r0 + 8) * HID + cc] =
                    make_float2(acc[mi][ni][2], acc[mi][ni][3]);
            }
        }
    )
}

__global__ void __launch_bounds__(256, 2) hmma_gemm_split(
    const __nv_bfloat16* __restrict__ Ahi, const __nv_bfloat16* __restrict__ Alo,
    const __nv_bfloat16* __restrict__ Whi, const __nv_bfloat16* __restrict__ Wlo,
    __nv_bfloat16* __restrict__ Chi, __nv_bfloat16* __restrict__ Clo) {
    GEMM_BODY(
        _Pragma("unroll")
        for (int mi = 0; mi < 4; ++mi) {
            int r0 = m0 + wm + mi * 16 + group;
            _Pragma("unroll")
            for (int ni = 0; ni < 4; ++ni) {
                int cc = n0 + wn + ni * 8 + tig * 2;
                store_split2(Chi, Clo, (size_t)r0 * HID + cc,
                             acc[mi][ni][0], acc[mi][ni][1]);
                store_split2(Chi, Clo, (size_t)(r0 + 8) * HID + cc,
                             acc[mi][ni][2], acc[mi][ni][3]);
            }
        }
    )
}

// ------------------------- pipelined HMMA flash attention --------------------
// smem (bf16 elems): Q hi/lo (128x72), K hi/lo x2 buffers, V hi/lo (row-major).
#define APAD 72
#define SQ_  (128 * APAD)
#define ATT_SMEM_BYTES (8 * SQ_ * 2 + 512 + 512 + 64)

__global__ void __launch_bounds__(256) attn_hmma(
    const __nv_bfloat16* __restrict__ Qhi_g, const __nv_bfloat16* __restrict__ Qlo_g,
    const __nv_bfloat16* __restrict__ Khi_g, const __nv_bfloat16* __restrict__ Klo_g,
    const __nv_bfloat16* __restrict__ Vhi_g, const __nv_bfloat16* __restrict__ Vlo_g,
    const int* __restrict__ qtid, const int* __restrict__ ktid,
    const int* __restrict__ mask,
    const float* __restrict__ tbias,
    __nv_bfloat16* __restrict__ Ohi, __nv_bfloat16* __restrict__ Olo) {
    extern __shared__ __nv_bfloat16 sm[];
    __nv_bfloat16* sQh = sm;
    __nv_bfloat16* sQl = sm + SQ_;
    // K buffers: buf0 at 2,3 ; buf1 at 4,5 ; V at 6,7
    float* sCb = (float*)((char*)sm + 8 * SQ_ * 2);
    int*   sKt = (int*)(sCb + 128);
    float* sTb = (float*)(sKt + 128);
    uint32_t smb = smem_u32(sm);

    int tid = threadIdx.x, w = tid >> 5, lane = tid & 31;
    int group = lane >> 2, tig = lane & 3;
    int b = blockIdx.z, h = blockIdx.y, q0 = blockIdx.x * 128;

    // ---- preload Q and K(0) via cp.async ----
    #pragma unroll
    for (int t = 0; t < 4; ++t) {
        int idx = tid + t * 256;              // 0..1023
        int row = idx >> 3, ch = idx & 7;
        size_t gq = (size_t)(b*NQ + q0 + row) * HID + h*HD + ch*8;
        uint32_t ds = (row * APAD + ch * 8) * 2;
        cpa16(smb + ds,             Qhi_g + gq);
        cpa16(smb + SQ_*2 + ds,     Qlo_g + gq);
    }
    CP_COMMIT();
    #pragma unroll
    for (int t = 0; t < 4; ++t) {
        int idx = tid + t * 256;
        int row = idx >> 3, ch = idx & 7;
        size_t gk = (size_t)(b*NK + row) * HID + h*HD + ch*8;
        uint32_t ds = (row * APAD + ch * 8) * 2;
        cpa16(smb + 2*SQ_*2 + ds, Khi_g + gk);
        cpa16(smb + 3*SQ_*2 + ds, Klo_g + gk);
    }
    CP_COMMIT();
    if (tid < 9) sTb[tid] = tbias[tid];
    CP_WAIT0();
    __syncthreads();

    int qt0 = qtid[q0 + w*16 + group];
    int qt1 = qtid[q0 + w*16 + group + 8];
    float t00 = sTb[qt0*3+0], t01 = sTb[qt0*3+1], t02 = sTb[qt0*3+2];
    float t10 = sTb[qt1*3+0], t11 = sTb[qt1*3+1], t12 = sTb[qt1*3+2];

    float m0 = M_INIT, m1 = M_INIT, l0 = 0.f, l1 = 0.f;
    float oacc[8][4] = {};
    int cur = 0;
    int ldm_m = lane >> 3, ldm_r = lane & 7;

    for (int kt = 0; kt < 32; ++kt) {
        int kv0 = kt * 128;
        // V(kt) copies
        #pragma unroll
        for (int t = 0; t < 4; ++t) {
            int idx = tid + t * 256;
            int row = idx >> 3, ch = idx & 7;
            size_t gv = (size_t)(b*NK + kv0 + row) * HID + h*HD + ch*8;
            uint32_t ds = (row * APAD + ch * 8) * 2;
            cpa16(smb + 6*SQ_*2 + ds, Vhi_g + gv);
            cpa16(smb + 7*SQ_*2 + ds, Vlo_g + gv);
        }
        CP_COMMIT();
        bool pre = (kt < 31);
        if (pre) {
            int nb = cur ^ 1;
            #pragma unroll
            for (int t = 0; t < 4; ++t) {
                int idx = tid + t * 256;
                int row = idx >> 3, ch = idx & 7;
                size_t gk = (size_t)(b*NK + kv0 + 128 + row) * HID + h*HD + ch*8;
                uint32_t ds = (row * APAD + ch * 8) * 2;
                cpa16(smb + (2 + 2*nb)*SQ_*2 + ds, Khi_g + gk);
                cpa16(smb + (3 + 2*nb)*SQ_*2 + ds, Klo_g + gk);
            }
            CP_COMMIT();
        }
        int mreg = 0, kreg = 0;
        if (tid < 128) {
            mreg = mask[b*NK + kv0 + tid];
            kreg = ktid[kv0 + tid];
        }

        // ---- S = Q @ K^T (split x3) on K buffer `cur` ----
        __nv_bfloat16* sKh = sm + (2 + 2*cur) * SQ_;
        __nv_bfloat16* sKl = sm + (3 + 2*cur) * SQ_;
        float sacc[16][4] = {};
        #pragma unroll
        for (int kc = 0; kc < 4; ++kc) {
            int ro = (w*16 + group) * APAD + kc*16 + tig*2;
            uint32_t ah0 = *(uint32_t*)&sQh[ro];
            uint32_t ah1 = *(uint32_t*)&sQh[ro + 8*APAD];
            uint32_t ah2 = *(uint32_t*)&sQh[ro + 8];
            uint32_t ah3 = *(uint32_t*)&sQh[ro + 8*APAD + 8];
            uint32_t al0 = *(uint32_t*)&sQl[ro];
            uint32_t al1 = *(uint32_t*)&sQl[ro + 8*APAD];
            uint32_t al2 = *(uint32_t*)&sQl[ro + 8];
            uint32_t al3 = *(uint32_t*)&sQl[ro + 8*APAD + 8];
            #pragma unroll
            for (int ni = 0; ni < 16; ++ni) {
                int bo = (ni*8 + group) * APAD + kc*16 + tig*2;
                uint32_t bh0 = *(uint32_t*)&sKh[bo];
                uint32_t bh1 = *(uint32_t*)&sKh[bo + 8];
                uint32_t bl0 = *(uint32_t*)&sKl[bo];
                uint32_t bl1 = *(uint32_t*)&sKl[bo + 8];
                mma_bf16(sacc[ni][0], sacc[ni][1], sacc[ni][2], sacc[ni][3],
                         ah0, ah1, ah2, ah3, bh0, bh1);
                mma_bf16(sacc[ni][0], sacc[ni][1], sacc[ni][2], sacc[ni][3],
                         ah0, ah1, ah2, ah3, bl0, bl1);
                mma_bf16(sacc[ni][0], sacc[ni][1], sacc[ni][2], sacc[ni][3],
                         al0, al1, al2, al3, bh0, bh1);
            }
        }

        // V ready; publish mask/ktid
        if (pre) { CP_WAIT1(); } else { CP_WAIT0(); }
        if (tid < 128) {
            sCb[tid] = mreg ? 0.f : NEG_BIG;
            sKt[tid] = kreg;
        }
        __syncthreads();

        // ---- epilogue + online softmax ----
        float mx0 = -3.0e38f, mx1 = -3.0e38f;
        #pragma unroll
        for (int ni = 0; ni < 16; ++ni) {
            int j0 = ni*8 + tig*2;
            float cb0 = sCb[j0], cb1 = sCb[j0+1];
            int kt0 = sKt[j0], kt1 = sKt[j0+1];
            float b00 = (kt0 == 0 ? t00 : kt0 == 1 ? t01 : t02) + cb0;
            float b01 = (kt1 == 0 ? t00 : kt1 == 1 ? t01 : t02) + cb1;
            float b10 = (kt0 == 0 ? t10 : kt0 == 1 ? t11 : t12) + cb0;
            float b11 = (kt1 == 0 ? t10 : kt1 == 1 ? t11 : t12) + cb1;
            sacc[ni][0] = sacc[ni][0] * 0.125f + b00;
            sacc[ni][1] = sacc[ni][1] * 0.125f + b01;
            sacc[ni][2] = sacc[ni][2] * 0.125f + b10;
            sacc[ni][3] = sacc[ni][3] * 0.125f + b11;
            mx0 = fmaxf(mx0, fmaxf(sacc[ni][0], sacc[ni][1]));
            mx1 = fmaxf(mx1, fmaxf(sacc[ni][2], sacc[ni][3]));
        }
        mx0 = fmaxf(mx0, __shfl_xor_sync(0xffffffffu, mx0, 1));
        mx0 = fmaxf(mx0, __shfl_xor_sync(0xffffffffu, mx0, 2));
        mx1 = fmaxf(mx1, __shfl_xor_sync(0xffffffffu, mx1, 1));
        mx1 = fmaxf(mx1, __shfl_xor_sync(0xffffffffu, mx1, 2));
        float mn0 = fmaxf(m0, mx0), mn1 = fmaxf(m1, mx1);
        float al_0 = __expf(m0 - mn0), al_1 = __expf(m1 - mn1);
        m0 = mn0; m1 = mn1;
        float sum0 = 0.f, sum1 = 0.f;
        #pragma unroll
        for (int ni = 0; ni < 16; ++ni) {
            float p0 = __expf(sacc[ni][0] - mn0);
            float p1 = __expf(sacc[ni][1] - mn0);
            float p2 = __expf(sacc[ni][2] - mn1);
            float p3 = __expf(sacc[ni][3] - mn1);
            sacc[ni][0] = p0; sacc[ni][1] = p1;
            sacc[ni][2] = p2; sacc[ni][3] = p3;
            sum0 += p0 + p1; sum1 += p2 + p3;
        }
        sum0 += __shfl_xor_sync(0xffffffffu, sum0, 1);
        sum0 += __shfl_xor_sync(0xffffffffu, sum0, 2);
        sum1 += __shfl_xor_sync(0xffffffffu, sum1, 1);
        sum1 += __shfl_xor_sync(0xffffffffu, sum1, 2);
        l0 = l0 * al_0 + sum0;
        l1 = l1 * al_1 + sum1;
        #pragma unroll
        for (int nd = 0; nd < 8; ++nd) {
            oacc[nd][0] *= al_0; oacc[nd][1] *= al_0;
            oacc[nd][2] *= al_1; oacc[nd][3] *= al_1;
        }

        // ---- O += P @ V via ldmatrix.x4.trans on row-major V ----
        uint32_t vbh = smb + 6*SQ_*2;
        uint32_t vbl = smb + 7*SQ_*2;
        #pragma unroll
        for (int kk = 0; kk < 8; ++kk) {
            uint32_t ph0 = pack_bf16x2(sacc[2*kk][0],   sacc[2*kk][1]);
            uint32_t ph1 = pack_bf16x2(sacc[2*kk][2],   sacc[2*kk][3]);
            uint32_t ph2 = pack_bf16x2(sacc[2*kk+1][0], sacc[2*kk+1][1]);
            uint32_t ph3 = pack_bf16x2(sacc[2*kk+1][2], sacc[2*kk+1][3]);
            uint32_t pl0 = pack_bf16x2_res(sacc[2*kk][0],   sacc[2*kk][1]);
            uint32_t pl1 = pack_bf16x2_res(sacc[2*kk][2],   sacc[2*kk][3]);
            uint32_t pl2 = pack_bf16x2_res(sacc[2*kk+1][0], sacc[2*kk+1][1]);
            uint32_t pl3 = pack_bf16x2_res(sacc[2*kk+1][2], sacc[2*kk+1][3]);
            int rowb = kk*16 + (ldm_m & 1)*8 + ldm_r;
            #pragma unroll
            for (int ndp = 0; ndp < 4; ++ndp) {
                uint32_t off = (uint32_t)(rowb * APAD + ndp*16 + (ldm_m >> 1)*8) * 2;
                uint32_t bh0, bh1, bh2, bh3, bl0, bl1, bl2, bl3;
                ldsm_x4_trans(bh0, bh1, bh2, bh3, vbh + off);
                ldsm_x4_trans(bl0, bl1, bl2, bl3, vbl + off);
                mma_bf16(oacc[2*ndp][0], oacc[2*ndp][1], oacc[2*ndp][2], oacc[2*ndp][3],
                         ph0, ph1, ph2, ph3, bh0, bh1);
                mma_bf16(oacc[2*ndp][0], oacc[2*ndp][1], oacc[2*ndp][2], oacc[2*ndp][3],
                         ph0, ph1, ph2, ph3, bl0, bl1);
                mma_bf16(oacc[2*ndp][0], oacc[2*ndp][1], oacc[2*ndp][2], oacc[2*ndp][3],
                         pl0, pl1, pl2, pl3, bh0, bh1);
                mma_bf16(oacc[2*ndp+1][0], oacc[2*ndp+1][1], oacc[2*ndp+1][2], oacc[2*ndp+1][3],
                         ph0, ph1, ph2, ph3, bh2, bh3);
                mma_bf16(oacc[2*ndp+1][0], oacc[2*ndp+1][1], oacc[2*ndp+1][2], oacc[2*ndp+1][3],
                         ph0, ph1, ph2, ph3, bl2, bl3);
                mma_bf16(oacc[2*ndp+1][0], oacc[2*ndp+1][1], oacc[2*ndp+1][2], oacc[2*ndp+1][3],
                         pl0, pl1, pl2, pl3, bh2, bh3);
            }
        }

        CP_WAIT0();           // K(kt+1) landed
        __syncthreads();      // V free, K(kt+1) visible
        cur ^= 1;
    }

    float inv0 = 1.0f / l0, inv1 = 1.0f / l1;
    int r0g = b*NQ + q0 + w*16 + group;
    #pragma unroll
    for (int nd = 0; nd < 8; ++nd) {
        int cc = h*HD + nd*8 + tig*2;
        store_split2(Ohi, Olo, (size_t)r0g * HID + cc,
                     oacc[nd][0]*inv0, oacc[nd][1]*inv0);
        store_split2(Ohi, Olo, (size_t)(r0g + 8) * HID + cc,
                     oacc[nd][2]*inv1, oacc[nd][3]*inv1);
    }
}

// ---------------------------------------------------------------------------
extern "C" void kernel_launch(void* const* d_in, const int* in_sizes, int n_in,
                              void* d_out, int out_size) {
    const float* queries = (const float*)d_in[0];
    const float* kv      = (const float*)d_in[1];
    const int*   qtid    = (const int*)d_in[2];
    const int*   ktid    = (const int*)d_in[3];
    const int*   mask    = (const int*)d_in[4];   // widened bool
    const float* Wq      = (const float*)d_in[5];
    const float* Wk      = (const float*)d_in[6];
    const float* Wv      = (const float*)d_in[7];
    const float* Wo      = (const float*)d_in[8];
    const float* qn_w    = (const float*)d_in[9];
    const float* qn_b    = (const float*)d_in[10];
    const float* kvn_w   = (const float*)d_in[11];
    const float* kvn_b   = (const float*)d_in[12];
    const float* on_w    = (const float*)d_in[13];
    const float* on_b    = (const float*)d_in[14];
    const float* tbias   = (const float*)d_in[15];
    float*       out     = (float*)d_out;

    float *proj;
    __nv_bfloat16 *qn_hi, *qn_lo, *kvn_hi, *kvn_lo;
    __nv_bfloat16 *q_hi, *q_lo, *k_hi, *k_lo, *v_hi, *v_lo;
    __nv_bfloat16 *att_hi, *att_lo, *w_hi, *w_lo;
    cudaGetSymbolAddress((void**)&proj,   g_proj);
    cudaGetSymbolAddress((void**)&qn_hi,  g_qn_hi);
    cudaGetSymbolAddress((void**)&qn_lo,  g_qn_lo);
    cudaGetSymbolAddress((void**)&kvn_hi, g_kvn_hi);
    cudaGetSymbolAddress((void**)&kvn_lo, g_kvn_lo);
    cudaGetSymbolAddress((void**)&q_hi,   g_q_hi);
    cudaGetSymbolAddress((void**)&q_lo,   g_q_lo);
    cudaGetSymbolAddress((void**)&k_hi,   g_k_hi);
    cudaGetSymbolAddress((void**)&k_lo,   g_k_lo);
    cudaGetSymbolAddress((void**)&v_hi,   g_v_hi);
    cudaGetSymbolAddress((void**)&v_lo,   g_v_lo);
    cudaGetSymbolAddress((void**)&att_hi, g_att_hi);
    cudaGetSymbolAddress((void**)&att_lo, g_att_lo);
    cudaGetSymbolAddress((void**)&w_hi,   g_w_hi);
    cudaGetSymbolAddress((void**)&w_lo,   g_w_lo);

    cudaFuncSetAttribute(hmma_gemm_f32, cudaFuncAttributeMaxDynamicSharedMemorySize,
                         GEMM_SMEM);
    cudaFuncSetAttribute(hmma_gemm_split, cudaFuncAttributeMaxDynamicSharedMemorySize,
                         GEMM_SMEM);
    cudaFuncSetAttribute(attn_hmma, cudaFuncAttributeMaxDynamicSharedMemorySize,
                         ATT_SMEM_BYTES);

    const int WN = HID * HID;

    // 1) LayerNorm + split-bf16 conversion of activations
    ln_cvt_kernel<<<B_ * NQ, 256>>>(queries, qn_hi, qn_lo, qn_w, qn_b);
    ln_cvt_kernel<<<B_ * NK, 256>>>(kv, kvn_hi, kvn_lo, kvn_w, kvn_b);

    // 2) weight conversion (hi/lo)
    cvt_kernel<<<WN/4/256, 256>>>(Wq, w_hi + 0*WN, w_lo + 0*WN, WN/4);
    cvt_kernel<<<WN/4/256, 256>>>(Wk, w_hi + 1*WN, w_lo + 1*WN, WN/4);
    cvt_kernel<<<WN/4/256, 256>>>(Wv, w_hi + 2*WN, w_lo + 2*WN, WN/4);
    cvt_kernel<<<WN/4/256, 256>>>(Wo, w_hi + 3*WN, w_lo + 3*WN, WN/4);

    // 3) projections -> split bf16 outputs
    hmma_gemm_split<<<dim3(8, (B_*NQ)/128), 256, GEMM_SMEM>>>(
        qn_hi, qn_lo, w_hi + 0*WN, w_lo + 0*WN, q_hi, q_lo);
    hmma_gemm_split<<<dim3(8, (B_*NK)/128), 256, GEMM_SMEM>>>(
        kvn_hi, kvn_lo, w_hi + 1*WN, w_lo + 1*WN, k_hi, k_lo);
    hmma_gemm_split<<<dim3(8, (B_*NK)/128), 256, GEMM_SMEM>>>(
        kvn_hi, kvn_lo, w_hi + 2*WN, w_lo + 2*WN, v_hi, v_lo);

    // 4) attention (pipelined HMMA flash)
    attn_hmma<<<dim3(NQ/128, HEADS, B_), 256, ATT_SMEM_BYTES>>>(
        q_hi, q_lo, k_hi, k_lo, v_hi, v_lo,
        qtid, ktid, mask, tbias, att_hi, att_lo);

    // 5) out projection (fp32 output)
    hmma_gemm_f32<<<dim3(8, (B_*NQ)/128), 256, GEMM_SMEM>>>(
        att_hi, att_lo, w_hi + 3*WN, w_lo + 3*WN, proj);

    // 6) residual + LN
    addln_kernel<<<B_ * NQ, 256>>>(queries, proj, out, on_w, on_b);
}

// round 10
// speedup vs baseline: 5.5021x; 2.3822x over previous
#include <cuda_runtime.h>
#include <cuda_fp16.h>
#include <cstdint>

// ---------------------------------------------------------------------------
// SVACrossAttentionLayer on GB300.  R9: whole tensor pipeline in fp16 single
// (no hi/lo split) -> 3x less tensor work.  fp32 accumulate everywhere;
// error budget calibrated from R7 data (predicted final rel_err ~3e-4).
// B=2, Nq=1024, Nk=4096, HID=1024, H=16, hd=64.
// ---------------------------------------------------------------------------

#define B_       2
#define NQ       1024
#define NK       4096
#define HID      1024
#define HEADS    16
#define HD       64
#define LN_EPS   1e-5f
#define NEG_BIG  (-1e30f)
#define M_INIT   (-1e9f)

// ------------------------- scratch (static, no allocs) ---------------------
__device__ float  g_proj[B_ * NQ * HID];
__device__ __half g_qn  [B_ * NQ * HID];
__device__ __half g_kvn [B_ * NK * HID];
__device__ __half g_q   [B_ * NQ * HID];
__device__ __half g_k   [B_ * NK * HID];
__device__ __half g_v   [B_ * NK * HID];
__device__ __half g_att [B_ * NQ * HID];
__device__ __half g_w   [4 * HID * HID];   // Wq,Wk,Wv,Wo (fp16)

// ------------------------- PTX helpers --------------------------------------
__device__ __forceinline__ void mma_f16(
    float& c0, float& c1, float& c2, float& c3,
    uint32_t a0, uint32_t a1, uint32_t a2, uint32_t a3,
    uint32_t b0, uint32_t b1) {
    asm volatile(
        "mma.sync.aligned.m16n8k16.row.col.f32.f16.f16.f32 "
        "{%0,%1,%2,%3}, {%4,%5,%6,%7}, {%8,%9}, {%0,%1,%2,%3};"
        : "+f"(c0), "+f"(c1), "+f"(c2), "+f"(c3)
        : "r"(a0), "r"(a1), "r"(a2), "r"(a3), "r"(b0), "r"(b1));
}
__device__ __forceinline__ void ldsm_x4_trans(
    uint32_t& r0, uint32_t& r1, uint32_t& r2, uint32_t& r3, uint32_t addr) {
    asm volatile("ldmatrix.sync.aligned.m8n8.x4.trans.shared.b16 {%0,%1,%2,%3}, [%4];"
                 : "=r"(r0), "=r"(r1), "=r"(r2), "=r"(r3) : "r"(addr));
}
__device__ __forceinline__ uint32_t smem_u32(const void* p) {
    uint32_t a;
    asm("{ .reg .u64 t; cvta.to.shared.u64 t, %1; cvt.u32.u64 %0, t; }"
        : "=r"(a) : "l"(p));
    return a;
}
__device__ __forceinline__ void cpa16(uint32_t dst, const void* src) {
    asm volatile("cp.async.cg.shared.global [%0], [%1], 16;" :: "r"(dst), "l"(src));
}
#define CP_COMMIT() asm volatile("cp.async.commit_group;" ::: "memory")
#define CP_WAIT0()  asm volatile("cp.async.wait_group 0;" ::: "memory")
#define CP_WAIT1()  asm volatile("cp.async.wait_group 1;" ::: "memory")

__device__ __forceinline__ uint32_t pack_f16x2(float a, float b) {
    __half2 h = __floats2half2_rn(a, b);
    return *(uint32_t*)&h;
}
__device__ __forceinline__ void store_h2(__half* p, size_t off, float a, float b) {
    *(__half2*)&p[off] = __floats2half2_rn(a, b);
}

// ------------------------- block reduce (256 thr) ---------------------------
__device__ __forceinline__ void block_reduce2(float& s, float& ss) {
    #pragma unroll
    for (int o = 16; o; o >>= 1) {
        s  += __shfl_xor_sync(0xffffffffu, s,  o);
        ss += __shfl_xor_sync(0xffffffffu, ss, o);
    }
    __shared__ float sh[2][8];
    int w = threadIdx.x >> 5, lane = threadIdx.x & 31;
    if (lane == 0) { sh[0][w] = s; sh[1][w] = ss; }
    __syncthreads();
    float ts = 0.f, tss = 0.f;
    #pragma unroll
    for (int k = 0; k < 8; ++k) { ts += sh[0][k]; tss += sh[1][k]; }
    s = ts; ss = tss;
    __syncthreads();
}

// ------------------------- LayerNorm -> fp16 --------------------------------
__global__ void __launch_bounds__(256) ln_cvt_kernel(
    const float* __restrict__ x, __half* __restrict__ y,
    const float* __restrict__ w, const float* __restrict__ b) {
    int row = blockIdx.x;
    int t = threadIdx.x;
    float4 v = ((const float4*)(x + (size_t)row * HID))[t];
    float s  = v.x + v.y + v.z + v.w;
    float ss = v.x*v.x + v.y*v.y + v.z*v.z + v.w*v.w;
    block_reduce2(s, ss);
    float mean = s * (1.0f / HID);
    float var  = ss * (1.0f / HID) - mean * mean;
    float rstd = rsqrtf(var + LN_EPS);
    float4 wv = ((const float4*)w)[t], bv = ((const float4*)b)[t];
    size_t off = (size_t)row * HID + t*4;
    store_h2(y, off,     (v.x - mean) * rstd * wv.x + bv.x,
                         (v.y - mean) * rstd * wv.y + bv.y);
    store_h2(y, off + 2, (v.z - mean) * rstd * wv.z + bv.z,
                         (v.w - mean) * rstd * wv.w + bv.w);
}

// ------------------------- fp32 -> fp16 (weights) ---------------------------
__global__ void __launch_bounds__(256) cvt_kernel(
    const float* __restrict__ x, __half* __restrict__ y, int n4) {
    int i = blockIdx.x * 256 + threadIdx.x;
    if (i >= n4) return;
    float4 v = ((const float4*)x)[i];
    store_h2(y, (size_t)i*4,     v.x, v.y);
    store_h2(y, (size_t)i*4 + 2, v.z, v.w);
}

// ------------------------- residual + LayerNorm ------------------------------
__global__ void __launch_bounds__(256) addln_kernel(
    const float* __restrict__ xq, const float* __restrict__ xp,
    float* __restrict__ y,
    const float* __restrict__ w, const float* __restrict__ b) {
    int row = blockIdx.x;
    int t = threadIdx.x;
    float4 a = ((const float4*)(xq + (size_t)row * HID))[t];
    float4 c = ((const float4*)(xp + (size_t)row * HID))[t];
    float4 v;
    v.x = a.x + c.x; v.y = a.y + c.y; v.z = a.z + c.z; v.w = a.w + c.w;
    float s  = v.x + v.y + v.z + v.w;
    float ss = v.x*v.x + v.y*v.y + v.z*v.z + v.w*v.w;
    block_reduce2(s, ss);
    float mean = s * (1.0f / HID);
    float var  = ss * (1.0f / HID) - mean * mean;
    float rstd = rsqrtf(var + LN_EPS);
    float4 wv = ((const float4*)w)[t], bv = ((const float4*)b)[t], o;
    o.x = (v.x - mean) * rstd * wv.x + bv.x;
    o.y = (v.y - mean) * rstd * wv.y + bv.y;
    o.z = (v.z - mean) * rstd * wv.z + bv.z;
    o.w = (v.w - mean) * rstd * wv.w + bv.w;
    ((float4*)(y + (size_t)row * HID))[t] = o;
}

// ------------------------- HMMA GEMM (fp16 single) --------------------------
// C[M,1024] = A[M,1024] @ W[1024,1024]^T.  128x128 block, BK=64, 8 warps.
#define GPAD 72
#define GEMM_SMEM (2 * 128 * GPAD * 2)

#define GEMM_BODY(EPILOGUE)                                                   \
    extern __shared__ __half smem[];                                          \
    __half* sA = smem;                                                        \
    __half* sW = smem + 128 * GPAD;                                           \
    int tid = threadIdx.x, wid = tid >> 5, lane = tid & 31;                   \
    int group = lane >> 2, tig = lane & 3;                                    \
    int m0 = blockIdx.y * 128, n0 = blockIdx.x * 128;                         \
    int wm = (wid >> 2) * 64, wn = (wid & 3) * 32;                            \
    float acc[4][4][4] = {};                                                  \
    for (int kt = 0; kt < 16; ++kt) {                                         \
        _Pragma("unroll")                                                     \
        for (int l = 0; l < 4; ++l) {                                         \
            int idx = tid + l * 256;                                          \
            int row = idx >> 3, c = idx & 7;                                  \
            size_t ga = (size_t)(m0 + row) * HID + kt * 64 + c * 8;           \
            size_t gw = (size_t)(n0 + row) * HID + kt * 64 + c * 8;           \
            *(uint4*)&sA[row * GPAD + c * 8] = *(const uint4*)&A[ga];         \
            *(uint4*)&sW[row * GPAD + c * 8] = *(const uint4*)&W[gw];         \
        }                                                                     \
        __syncthreads();                                                      \
        _Pragma("unroll")                                                     \
        for (int ks = 0; ks < 4; ++ks) {                                      \
            int kb = ks * 16;                                                 \
            uint32_t af[4][4];                                                \
            _Pragma("unroll")                                                 \
            for (int mi = 0; mi < 4; ++mi) {                                  \
                int r0 = wm + mi * 16 + group;                                \
                int o00 = r0 * GPAD + kb + tig * 2;                           \
                int o10 = (r0 + 8) * GPAD + kb + tig * 2;                     \
                af[mi][0] = *(uint32_t*)&sA[o00];                             \
                af[mi][1] = *(uint32_t*)&sA[o10];                             \
                af[mi][2] = *(uint32_t*)&sA[o00 + 8];                         \
                af[mi][3] = *(uint32_t*)&sA[o10 + 8];                         \
            }                                                                 \
            _Pragma("unroll")                                                 \
            for (int ni = 0; ni < 4; ++ni) {                                  \
                int nr = wn + ni * 8 + group;                                 \
                int ob = nr * GPAD + kb + tig * 2;                            \
                uint32_t b0 = *(uint32_t*)&sW[ob];                            \
                uint32_t b1 = *(uint32_t*)&sW[ob + 8];                        \
                _Pragma("unroll")                                             \
                for (int mi = 0; mi < 4; ++mi)                                \
                    mma_f16(acc[mi][ni][0], acc[mi][ni][1],                   \
                            acc[mi][ni][2], acc[mi][ni][3],                   \
                            af[mi][0], af[mi][1], af[mi][2], af[mi][3],       \
                            b0, b1);                                          \
            }                                                                 \
        }                                                                     \
        __syncthreads();                                                      \
    }                                                                         \
    EPILOGUE

__global__ void __launch_bounds__(256, 2) hmma_gemm_h(
    const __half* __restrict__ A, const __half* __restrict__ W,
    __half* __restrict__ C) {
    GEMM_BODY(
        _Pragma("unroll")
        for (int mi = 0; mi < 4; ++mi) {
            int r0 = m0 + wm + mi * 16 + group;
            _Pragma("unroll")
            for (int ni = 0; ni < 4; ++ni) {
                int cc = n0 + wn + ni * 8 + tig * 2;
                store_h2(C, (size_t)r0 * HID + cc,       acc[mi][ni][0], acc[mi][ni][1]);
                store_h2(C, (size_t)(r0 + 8) * HID + cc, acc[mi][ni][2], acc[mi][ni][3]);
            }
        }
    )
}

__global__ void __launch_bounds__(256, 2) hmma_gemm_f(
    const __half* __restrict__ A, const __half* __restrict__ W,
    float* __restrict__ C) {
    GEMM_BODY(
        _Pragma("unroll")
        for (int mi = 0; mi < 4; ++mi) {
            int r0 = m0 + wm + mi * 16 + group;
            _Pragma("unroll")
            for (int ni = 0; ni < 4; ++ni) {
                int cc = n0 + wn + ni * 8 + tig * 2;
                *(float2*)&C[(size_t)r0 * HID + cc] =
                    make_float2(acc[mi][ni][0], acc[mi][ni][1]);
                *(float2*)&C[(size_t)(r0 + 8) * HID + cc] =
                    make_float2(acc[mi][ni][2], acc[mi][ni][3]);
            }
        }
    )
}

// ------------------------- pipelined fp16 flash attention --------------------
// smem (halves): Q (128x72), K x2 buffers, V.  + bias table.
#define APAD 72
#define SQ_  (128 * APAD)
#define ATT_SMEM_BYTES (4 * SQ_ * 2 + 3*128*4 + 64)

__global__ void __launch_bounds__(256) attn_hmma(
    const __half* __restrict__ Qg, const __half* __restrict__ Kg,
    const __half* __restrict__ Vg,
    const int* __restrict__ qtid, const int* __restrict__ ktid,
    const int* __restrict__ mask,
    const float* __restrict__ tbias,
    __half* __restrict__ O) {
    extern __shared__ __half sm[];
    __half* sQ = sm;                 // K0 at 1*SQ_, K1 at 2*SQ_, V at 3*SQ_
    float* sB  = (float*)((char*)sm + 4 * SQ_ * 2);   // [3][128] bias table
    float* sTb = sB + 3 * 128;
    uint32_t smb = smem_u32(sm);

    int tid = threadIdx.x, w = tid >> 5, lane = tid & 31;
    int group = lane >> 2, tig = lane & 3;
    int b = blockIdx.z, h = blockIdx.y, q0 = blockIdx.x * 128;

    // ---- preload Q and K(0) via cp.async ----
    #pragma unroll
    for (int t = 0; t < 4; ++t) {
        int idx = tid + t * 256;
        int row = idx >> 3, ch = idx & 7;
        size_t gq = (size_t)(b*NQ + q0 + row) * HID + h*HD + ch*8;
        cpa16(smb + (row * APAD + ch * 8) * 2, Qg + gq);
    }
    CP_COMMIT();
    #pragma unroll
    for (int t = 0; t < 4; ++t) {
        int idx = tid + t * 256;
        int row = idx >> 3, ch = idx & 7;
        size_t gk = (size_t)(b*NK + row) * HID + h*HD + ch*8;
        cpa16(smb + SQ_*2 + (row * APAD + ch * 8) * 2, Kg + gk);
    }
    CP_COMMIT();
    if (tid < 9) sTb[tid] = tbias[tid];
    CP_WAIT0();
    __syncthreads();

    int qt0 = qtid[q0 + w*16 + group];
    int qt1 = qtid[q0 + w*16 + group + 8];

    float m0 = M_INIT, m1 = M_INIT, l0 = 0.f, l1 = 0.f;
    float oacc[8][4] = {};
    int cur = 0;
    int ldm_m = lane >> 3, ldm_r = lane & 7;

    for (int kt = 0; kt < 32; ++kt) {
        int kv0 = kt * 128;
        // V(kt) copies
        #pragma unroll
        for (int t = 0; t < 4; ++t) {
            int idx = tid + t * 256;
            int row = idx >> 3, ch = idx & 7;
            size_t gv = (size_t)(b*NK + kv0 + row) * HID + h*HD + ch*8;
            cpa16(smb + 3*SQ_*2 + (row * APAD + ch * 8) * 2, Vg + gv);
        }
        CP_COMMIT();
        bool pre = (kt < 31);
        if (pre) {
            int nb = cur ^ 1;
            #pragma unroll
            for (int t = 0; t < 4; ++t) {
                int idx = tid + t * 256;
                int row = idx >> 3, ch = idx & 7;
                size_t gk = (size_t)(b*NK + kv0 + 128 + row) * HID + h*HD + ch*8;
                cpa16(smb + (1 + nb)*SQ_*2 + (row * APAD + ch * 8) * 2, Kg + gk);
            }
            CP_COMMIT();
        }
        int mreg = 0, kreg = 0;
        if (tid < 128) {
            mreg = mask[b*NK + kv0 + tid];
            kreg = ktid[kv0 + tid];
        }

        // ---- S = Q @ K^T (fp16 single) ----
        __half* sK = sm + (1 + cur) * SQ_;
        float sacc[16][4] = {};
        #pragma unroll
        for (int kc = 0; kc < 4; ++kc) {
            int ro = (w*16 + group) * APAD + kc*16 + tig*2;
            uint32_t a0 = *(uint32_t*)&sQ[ro];
            uint32_t a1 = *(uint32_t*)&sQ[ro + 8*APAD];
            uint32_t a2 = *(uint32_t*)&sQ[ro + 8];
            uint32_t a3 = *(uint32_t*)&sQ[ro + 8*APAD + 8];
            #pragma unroll
            for (int ni = 0; ni < 16; ++ni) {
                int bo = (ni*8 + group) * APAD + kc*16 + tig*2;
                uint32_t b0 = *(uint32_t*)&sK[bo];
                uint32_t b1 = *(uint32_t*)&sK[bo + 8];
                mma_f16(sacc[ni][0], sacc[ni][1], sacc[ni][2], sacc[ni][3],
                        a0, a1, a2, a3, b0, b1);
            }
        }

        // V ready; publish bias table (tb[q][ktype] + maskbias)
        if (pre) { CP_WAIT1(); } else { CP_WAIT0(); }
        if (tid < 128) {
            float cb = mreg ? 0.f : NEG_BIG;
            sB[0*128 + tid] = sTb[0*3 + kreg] + cb;
            sB[1*128 + tid] = sTb[1*3 + kreg] + cb;
            sB[2*128 + tid] = sTb[2*3 + kreg] + cb;
        }
        __syncthreads();

        // ---- epilogue + online softmax ----
        float mx0 = -3.0e38f, mx1 = -3.0e38f;
        const float* b0r = sB + qt0*128;
        const float* b1r = sB + qt1*128;
        #pragma unroll
        for (int ni = 0; ni < 16; ++ni) {
            int j0 = ni*8 + tig*2;
            sacc[ni][0] = sacc[ni][0] * 0.125f + b0r[j0];
            sacc[ni][1] = sacc[ni][1] * 0.125f + b0r[j0+1];
            sacc[ni][2] = sacc[ni][2] * 0.125f + b1r[j0];
            sacc[ni][3] = sacc[ni][3] * 0.125f + b1r[j0+1];
            mx0 = fmaxf(mx0, fmaxf(sacc[ni][0], sacc[ni][1]));
            mx1 = fmaxf(mx1, fmaxf(sacc[ni][2], sacc[ni][3]));
        }
        mx0 = fmaxf(mx0, __shfl_xor_sync(0xffffffffu, mx0, 1));
        mx0 = fmaxf(mx0, __shfl_xor_sync(0xffffffffu, mx0, 2));
        mx1 = fmaxf(mx1, __shfl_xor_sync(0xffffffffu, mx1, 1));
        mx1 = fmaxf(mx1, __shfl_xor_sync(0xffffffffu, mx1, 2));
        float mn0 = fmaxf(m0, mx0), mn1 = fmaxf(m1, mx1);
        float al_0 = __expf(m0 - mn0), al_1 = __expf(m1 - mn1);
        m0 = mn0; m1 = mn1;
        float sum0 = 0.f, sum1 = 0.f;
        #pragma unroll
        for (int ni = 0; ni < 16; ++ni) {
            float p0 = __expf(sacc[ni][0] - mn0);
            float p1 = __expf(sacc[ni][1] - mn0);
            float p2 = __expf(sacc[ni][2] - mn1);
            float p3 = __expf(sacc[ni][3] - mn1);
            sacc[ni][0] = p0; sacc[ni][1] = p1;
            sacc[ni][2] = p2; sacc[ni][3] = p3;
            sum0 += p0 + p1; sum1 += p2 + p3;
        }
        sum0 += __shfl_xor_sync(0xffffffffu, sum0, 1);
        sum0 += __shfl_xor_sync(0xffffffffu, sum0, 2);
        sum1 += __shfl_xor_sync(0xffffffffu, sum1, 1);
        sum1 += __shfl_xor_sync(0xffffffffu, sum1, 2);
        l0 = l0 * al_0 + sum0;
        l1 = l1 * al_1 + sum1;
        #pragma unroll
        for (int nd = 0; nd < 8; ++nd) {
            oacc[nd][0] *= al_0; oacc[nd][1] *= al_0;
            oacc[nd][2] *= al_1; oacc[nd][3] *= al_1;
        }

        // ---- O += P @ V via ldmatrix.x4.trans on row-major V ----
        uint32_t vb = smb + 3*SQ_*2;
        #pragma unroll
        for (int kk = 0; kk < 8; ++kk) {
            uint32_t p0 = pack_f16x2(sacc[2*kk][0],   sacc[2*kk][1]);
            uint32_t p1 = pack_f16x2(sacc[2*kk][2],   sacc[2*kk][3]);
            uint32_t p2 = pack_f16x2(sacc[2*kk+1][0], sacc[2*kk+1][1]);
            uint32_t p3 = pack_f16x2(sacc[2*kk+1][2], sacc[2*kk+1][3]);
            int rowb = kk*16 + (ldm_m & 1)*8 + ldm_r;
            #pragma unroll
            for (int ndp = 0; ndp < 4; ++ndp) {
                uint32_t off = (uint32_t)(rowb * APAD + ndp*16 + (ldm_m >> 1)*8) * 2;
                uint32_t v0, v1, v2, v3;
                ldsm_x4_trans(v0, v1, v2, v3, vb + off);
                mma_f16(oacc[2*ndp][0], oacc[2*ndp][1],
                        oacc[2*ndp][2], oacc[2*ndp][3],
                        p0, p1, p2, p3, v0, v1);
                mma_f16(oacc[2*ndp+1][0], oacc[2*ndp+1][1],
                        oacc[2*ndp+1][2], oacc[2*ndp+1][3],
                        p0, p1, p2, p3, v2, v3);
            }
        }

        CP_WAIT0();           // K(kt+1) landed
        __syncthreads();      // V free, K(kt+1) visible
        cur ^= 1;
    }

    float inv0 = 1.0f / l0, inv1 = 1.0f / l1;
    int r0g = b*NQ + q0 + w*16 + group;
    #pragma unroll
    for (int nd = 0; nd < 8; ++nd) {
        int cc = h*HD + nd*8 + tig*2;
        store_h2(O, (size_t)r0g * HID + cc,       oacc[nd][0]*inv0, oacc[nd][1]*inv0);
        store_h2(O, (size_t)(r0g + 8) * HID + cc, oacc[nd][2]*inv1, oacc[nd][3]*inv1);
    }
}

// ---------------------------------------------------------------------------
extern "C" void kernel_launch(void* const* d_in, const int* in_sizes, int n_in,
                              void* d_out, int out_size) {
    const float* queries = (const float*)d_in[0];
    const float* kv      = (const float*)d_in[1];
    const int*   qtid    = (const int*)d_in[2];
    const int*   ktid    = (const int*)d_in[3];
    const int*   mask    = (const int*)d_in[4];   // widened bool
    const float* Wq      = (const float*)d_in[5];
    const float* Wk      = (const float*)d_in[6];
    const float* Wv      = (const float*)d_in[7];
    const float* Wo      = (const float*)d_in[8];
    const float* qn_w    = (const float*)d_in[9];
    const float* qn_b    = (const float*)d_in[10];
    const float* kvn_w   = (const float*)d_in[11];
    const float* kvn_b   = (const float*)d_in[12];
    const float* on_w    = (const float*)d_in[13];
    const float* on_b    = (const float*)d_in[14];
    const float* tbias   = (const float*)d_in[15];
    float*       out     = (float*)d_out;

    float *proj;
    __half *qn, *kvn, *q, *k, *v, *att, *wgt;
    cudaGetSymbolAddress((void**)&proj, g_proj);
    cudaGetSymbolAddress((void**)&qn,   g_qn);
    cudaGetSymbolAddress((void**)&kvn,  g_kvn);
    cudaGetSymbolAddress((void**)&q,    g_q);
    cudaGetSymbolAddress((void**)&k,    g_k);
    cudaGetSymbolAddress((void**)&v,    g_v);
    cudaGetSymbolAddress((void**)&att,  g_att);
    cudaGetSymbolAddress((void**)&wgt,  g_w);

    cudaFuncSetAttribute(hmma_gemm_h, cudaFuncAttributeMaxDynamicSharedMemorySize,
                         GEMM_SMEM);
    cudaFuncSetAttribute(hmma_gemm_f, cudaFuncAttributeMaxDynamicSharedMemorySize,
                         GEMM_SMEM);
    cudaFuncSetAttribute(attn_hmma, cudaFuncAttributeMaxDynamicSharedMemorySize,
                         ATT_SMEM_BYTES);

    const int WN = HID * HID;

    // 1) LayerNorm -> fp16
    ln_cvt_kernel<<<B_ * NQ, 256>>>(queries, qn, qn_w, qn_b);
    ln_cvt_kernel<<<B_ * NK, 256>>>(kv, kvn, kvn_w, kvn_b);

    // 2) weights -> fp16
    cvt_kernel<<<WN/4/256, 256>>>(Wq, wgt + 0*WN, WN/4);
    cvt_kernel<<<WN/4/256, 256>>>(Wk, wgt + 1*WN, WN/4);
    cvt_kernel<<<WN/4/256, 256>>>(Wv, wgt + 2*WN, WN/4);
    cvt_kernel<<<WN/4/256, 256>>>(Wo, wgt + 3*WN, WN/4);

    // 3) projections (fp16 single-term)
    hmma_gemm_h<<<dim3(8, (B_*NQ)/128), 256, GEMM_SMEM>>>(qn,  wgt + 0*WN, q);
    hmma_gemm_h<<<dim3(8, (B_*NK)/128), 256, GEMM_SMEM>>>(kvn, wgt + 1*WN, k);
    hmma_gemm_h<<<dim3(8, (B_*NK)/128), 256, GEMM_SMEM>>>(kvn, wgt + 2*WN, v);

    // 4) attention (fp16 flash, pipelined)
    attn_hmma<<<dim3(NQ/128, HEADS, B_), 256, ATT_SMEM_BYTES>>>(
        q, k, v, qtid, ktid, mask, tbias, att);

    // 5) out projection (fp32 output)
    hmma_gemm_f<<<dim3(8, (B_*NQ)/128), 256, GEMM_SMEM>>>(att, wgt + 3*WN, proj);

    // 6) residual + LN
    addln_kernel<<<B_ * NQ, 256>>>(queries, proj, out, on_w, on_b);
}